// round 14
// baseline (speedup 1.0000x reference)
#include <cuda_runtime.h>
#include <cuda_fp16.h>
#include <math.h>
#include <stdint.h>

#define NPTS 8192
#define DIM 256
#define KC 64
#define NCHUNK (DIM / KC)
#define RPB 4
#define SM_SOFTMIN (RPB * 16384)   // 64 KB staged G / lists
#define GEMM_SMEM 65536            // 2-stage pipeline (R12 proven)
#define CAP 4096                   // shortlist cap per row (16 KB packed)
#define EPS_F 0.0025f
#define NEED_COST 0.069314718f     // 40 * EPS_F * ln2
#define DRIFT_BUDGET 0.06f
#define DELTA_BUILD (NEED_COST + 2.0f * DRIFT_BUDGET + 0.01f)

// ---------------- static device scratch (no allocation allowed) ----------------
__device__ float  d_wc[DIM];
__device__ __half d_anh[(size_t)NPTS * DIM];
__device__ __half d_bnh[(size_t)NPTS * DIM];
__device__ __half d_Gxy[(size_t)NPTS * NPTS];
__device__ __half d_Gyx[(size_t)NPTS * NPTS];
__device__ __half d_Gxx[(size_t)NPTS * NPTS];
__device__ __half d_Gyy[(size_t)NPTS * NPTS];
__device__ float  d_f[2][NPTS];
__device__ float  d_g[2][NPTS];
__device__ float  d_fxx[2][NPTS];
__device__ float  d_gyy[2][NPTS];
__device__ float  d_ffin[NPTS], d_gfin[NPTS], d_xfin[NPTS], d_yfin[NPTS];
// u-based shortlist machinery (variant: 0=Gxx/fxx, 1=Gyy/gyy, 2=Gxy/g->f, 3=Gyx/f->g)
__device__ uint32_t d_list[4][NPTS][CAP];   // packed {col<<16 | G halfbits}
__device__ int      d_cnt[4][NPTS];         // -1 => dense row
__device__ float    d_potref[4][NPTS];      // pot snapshot at build time
__device__ int      d_ok[4];                // drift within budget?

__device__ __forceinline__ float ex2f_fast(float x) {
    float y; asm("ex2.approx.ftz.f32 %0, %1;" : "=f"(y) : "f"(x)); return y;
}
__device__ __forceinline__ uint32_t smem_u32(const void* p) {
    uint32_t a;
    asm("{ .reg .u64 t; cvta.to.shared.u64 t, %1; cvt.u32.u64 %0, t; }" : "=r"(a) : "l"(p));
    return a;
}
__device__ __forceinline__ void cp_async16(uint32_t dst, const void* src) {
    asm volatile("cp.async.cg.shared.global [%0], [%1], 16;" :: "r"(dst), "l"(src) : "memory");
}
#define LDMX4(r, addr)                                                          \
    asm volatile("ldmatrix.sync.aligned.m8n8.x4.shared.b16 {%0,%1,%2,%3}, [%4];" \
                 : "=r"((r)[0]), "=r"((r)[1]), "=r"((r)[2]), "=r"((r)[3])        \
                 : "r"(addr))

// ---------------- prep ----------------
__global__ void wprep_kernel(const float* __restrict__ w) {
    __shared__ float sh[DIM];
    int t = threadIdx.x;
    float c = fminf(fmaxf(w[t], 0.0f), 2.0f);
    sh[t] = c;
    __syncthreads();
    for (int off = DIM / 2; off > 0; off >>= 1) {
        if (t < off) sh[t] += sh[t + off];
        __syncthreads();
    }
    d_wc[t] = c * ((float)DIM / sh[0]);
}

__global__ void rownorm_kernel(const float* __restrict__ x1, const float* __restrict__ x2) {
    __shared__ float sh[DIM];
    int b = blockIdx.x, t = threadIdx.x;
    float v;
    if (b < NPTS) v = d_wc[t] * x1[(size_t)b * DIM + t];
    else          v = x2[(size_t)(b - NPTS) * DIM + t];
    sh[t] = v * v;
    __syncthreads();
    for (int off = DIM / 2; off > 0; off >>= 1) {
        if (t < off) sh[t] += sh[t + off];
        __syncthreads();
    }
    float inv = 1.0f / (sqrtf(sh[0]) + 1e-12f);
    __half h = __float2half_rn(v * inv);
    if (b < NPTS) d_anh[(size_t)b * DIM + t] = h;
    else          d_bnh[(size_t)(b - NPTS) * DIM + t] = h;
}

__global__ void zero_kernel() {
    int i = blockIdx.x * blockDim.x + threadIdx.x;
    if (i < NPTS) {
        d_f[0][i] = 0.0f; d_g[0][i] = 0.0f;
        d_fxx[0][i] = 0.0f; d_gyy[0][i] = 0.0f;
    }
}

// ---------------- HMMA GEMM: 3 problems in one launch (R12 proven) ----------------
struct GArgs {
    const __half* A[3];
    const __half* B[3];
    __half*       C[3];
    __half*       CT[3];
    int           sym[3];
};

__global__ void __launch_bounds__(256, 2) gemm_mma(GArgs ga) {
    extern __shared__ char smem[];
    const int prob = blockIdx.z;
    const int btx = blockIdx.x, bty = blockIdx.y;
    const int sym = ga.sym[prob];
    if (sym && btx > bty) return;
    const __half* A  = ga.A[prob];
    const __half* B  = ga.B[prob];
    __half*       C  = ga.C[prob];
    __half*       CT = ga.CT[prob];

    const uint32_t smem_base = smem_u32(smem);
    const int tid = threadIdx.x;
    const int wid = tid >> 5, lane = tid & 31;
    const int warp_m = wid >> 2, warp_n = wid & 3;
    const int rowBase = bty * 128;
    const int colBase = btx * 128;

    const int mat = lane >> 3, rin = lane & 7;
    const int a_row_in = (mat & 1) * 8 + rin;
    const int a_kh     = (mat >> 1) * 8;
    const int b_row_in = (mat >> 1) * 8 + rin;
    const int b_kh     = (mat & 1) * 8;

    float acc[4][4][4];
#pragma unroll
    for (int mi = 0; mi < 4; ++mi)
#pragma unroll
        for (int ni = 0; ni < 4; ++ni)
#pragma unroll
            for (int q = 0; q < 4; ++q) acc[mi][ni][q] = 0.0f;

#define ISSUE_CHUNK(c, b) do {                                                  \
        const __half* Asrc_ = A + (size_t)rowBase * DIM + (c) * KC;             \
        const __half* Bsrc_ = B + (size_t)colBase * DIM + (c) * KC;             \
        uint32_t Ab_ = smem_base + (b) * 32768;                                 \
        uint32_t Bb_ = Ab_ + 16384;                                             \
        _Pragma("unroll")                                                       \
        for (int q_ = 0; q_ < 4; ++q_) {                                        \
            int i_ = q_ * 256 + tid;                                            \
            int r_ = i_ >> 3, cw_ = i_ & 7;                                     \
            uint32_t off_ = r_ * 128 + (((uint32_t)(cw_ ^ (r_ & 7))) << 4);     \
            cp_async16(Ab_ + off_, Asrc_ + (size_t)r_ * DIM + cw_ * 8);         \
            cp_async16(Bb_ + off_, Bsrc_ + (size_t)r_ * DIM + cw_ * 8);         \
        }                                                                       \
        asm volatile("cp.async.commit_group;" ::: "memory");                    \
    } while (0)

    ISSUE_CHUNK(0, 0);
#pragma unroll
    for (int c = 0; c < NCHUNK; ++c) {
        if (c + 1 < NCHUNK) {
            ISSUE_CHUNK(c + 1, (c + 1) & 1);
            asm volatile("cp.async.wait_group 1;" ::: "memory");
        } else {
            asm volatile("cp.async.wait_group 0;" ::: "memory");
        }
        __syncthreads();
        uint32_t Ab = smem_base + (c & 1) * 32768;
        uint32_t Bb = Ab + 16384;
#pragma unroll
        for (int ks = 0; ks < 4; ++ks) {
            uint32_t bf[2][4];
#pragma unroll
            for (int p = 0; p < 2; ++p) {
                int nrow = warp_n * 32 + p * 16 + b_row_in;
                int kcol = ks * 16 + b_kh;
                uint32_t addr = Bb + nrow * 128 + ((uint32_t)((kcol >> 3) ^ (nrow & 7)) << 4);
                LDMX4(bf[p], addr);
            }
#pragma unroll
            for (int mi = 0; mi < 4; ++mi) {
                uint32_t af[4];
                int arow = warp_m * 64 + mi * 16 + a_row_in;
                int kcol = ks * 16 + a_kh;
                uint32_t addr = Ab + arow * 128 + ((uint32_t)((kcol >> 3) ^ (arow & 7)) << 4);
                LDMX4(af, addr);
#pragma unroll
                for (int ni = 0; ni < 4; ++ni) {
                    asm volatile(
                        "mma.sync.aligned.m16n8k16.row.col.f32.f16.f16.f32 "
                        "{%0,%1,%2,%3}, {%4,%5,%6,%7}, {%8,%9}, {%0,%1,%2,%3};"
                        : "+f"(acc[mi][ni][0]), "+f"(acc[mi][ni][1]),
                          "+f"(acc[mi][ni][2]), "+f"(acc[mi][ni][3])
                        : "r"(af[0]), "r"(af[1]), "r"(af[2]), "r"(af[3]),
                          "r"(bf[ni >> 1][(ni & 1) * 2]), "r"(bf[ni >> 1][(ni & 1) * 2 + 1]));
                }
            }
        }
        __syncthreads();
    }
#undef ISSUE_CHUNK

    __half* stage = (__half*)smem;
#pragma unroll
    for (int mi = 0; mi < 4; ++mi)
#pragma unroll
        for (int ni = 0; ni < 4; ++ni) {
            int row = warp_m * 64 + mi * 16 + (lane >> 2);
            int col = warp_n * 32 + ni * 8 + 2 * (lane & 3);
            __half2 lo = __floats2half2_rn(acc[mi][ni][0], acc[mi][ni][1]);
            __half2 hi = __floats2half2_rn(acc[mi][ni][2], acc[mi][ni][3]);
            *(__half2*)(stage + row * 136 + col)       = lo;
            *(__half2*)(stage + (row + 8) * 136 + col) = hi;
        }
    __syncthreads();
#pragma unroll
    for (int i = tid; i < 2048; i += 256) {
        int r = i >> 4, ch = i & 15;
        uint4 v = *(uint4*)(stage + r * 136 + ch * 8);
        *(uint4*)(C + (size_t)(rowBase + r) * NPTS + colBase + ch * 8) = v;
    }

    if (!(sym && btx == bty)) {
        __syncthreads();
#pragma unroll
        for (int mi = 0; mi < 4; ++mi)
#pragma unroll
            for (int ni = 0; ni < 4; ++ni) {
                int row = warp_m * 64 + mi * 16 + (lane >> 2);
                int col = warp_n * 32 + ni * 8 + 2 * (lane & 3);
                stage[col * 136 + row]           = __float2half_rn(acc[mi][ni][0]);
                stage[(col + 1) * 136 + row]     = __float2half_rn(acc[mi][ni][1]);
                stage[col * 136 + row + 8]       = __float2half_rn(acc[mi][ni][2]);
                stage[(col + 1) * 136 + row + 8] = __float2half_rn(acc[mi][ni][3]);
            }
        __syncthreads();
#pragma unroll
        for (int i = tid; i < 2048; i += 256) {
            int r = i >> 4, ch = i & 15;
            uint4 v = *(uint4*)(stage + r * 136 + ch * 8);
            *(uint4*)(CT + (size_t)(colBase + r) * NPTS + rowBase + ch * 8) = v;
        }
    }
}

// ---------------- dense softmin (R12 proven: cp.async staged, half2 pass A) ----------------
struct SMArgs {
    const __half* G[4];
    const float*  pot[4];
    const float*  oldpot[4];
    float*        out[4];
    int           avg[4];
};

__global__ void __launch_bounds__(256, 3) softmin4(SMArgs args, float eps) {
    extern __shared__ char smg[];
    const uint32_t smg_u = smem_u32(smg);
    const int var  = blockIdx.y;
    const int row0 = blockIdx.x * RPB;
    const int tid  = threadIdx.x;
    const int lane = tid & 31, wid = tid >> 5;

    const float L2E = 1.4426950408889634f;
    const float c1 = L2E / eps;
    const float c0 = -c1;

    const __half* Gbase = args.G[var];
#pragma unroll
    for (int r = 0; r < RPB; ++r) {
        const __half* Gr = Gbase + (size_t)(row0 + r) * NPTS;
#pragma unroll
        for (int q = 0; q < 4; ++q) {
            int idx = q * 256 + tid;
            cp_async16(smg_u + r * 16384 + idx * 16, Gr + idx * 8);
        }
    }
    asm volatile("cp.async.commit_group;" ::: "memory");

    const float* pot = args.pot[var];
    float pp[32];
#pragma unroll
    for (int it = 0; it < 4; ++it) {
        int idx = it * 256 + tid;
        float4 a = ((const float4*)pot)[2 * idx];
        float4 b = ((const float4*)pot)[2 * idx + 1];
        pp[8 * it + 0] = fmaf(a.x, c1, c0); pp[8 * it + 1] = fmaf(a.y, c1, c0);
        pp[8 * it + 2] = fmaf(a.z, c1, c0); pp[8 * it + 3] = fmaf(a.w, c1, c0);
        pp[8 * it + 4] = fmaf(b.x, c1, c0); pp[8 * it + 5] = fmaf(b.y, c1, c0);
        pp[8 * it + 6] = fmaf(b.z, c1, c0); pp[8 * it + 7] = fmaf(b.w, c1, c0);
    }
    __half2 pph2[16];
#pragma unroll
    for (int j = 0; j < 16; ++j)
        pph2[j] = __floats2half2_rn(pp[2 * j], pp[2 * j + 1]);
    const __half2 c1h2 = __floats2half2_rn(c1, c1);

    asm volatile("cp.async.wait_group 0;" ::: "memory");

    __shared__ float sA[RPB][8];
    __shared__ float sS[RPB][8];

    float wtm[RPB];
#pragma unroll
    for (int r = 0; r < RPB; ++r) {
        __half2 mh = __floats2half2_rn(-60000.0f, -60000.0f);
#pragma unroll
        for (int it = 0; it < 4; ++it) {
            uint4 q = *(const uint4*)(smg + r * 16384 + (it * 256 + tid) * 16);
            const __half2* g2 = (const __half2*)&q;
#pragma unroll
            for (int k = 0; k < 4; ++k)
                mh = __hmax2(mh, __hfma2(g2[k], c1h2, pph2[it * 4 + k]));
        }
        float2 mf = __half22float2(mh);
        float tm = fmaxf(mf.x, mf.y);
#pragma unroll
        for (int off = 16; off > 0; off >>= 1)
            tm = fmaxf(tm, __shfl_xor_sync(0xffffffffu, tm, off));
        wtm[r] = tm;
        if (lane == 0) sA[r][wid] = tm;
    }
    __syncthreads();
    float M[RPB];
#pragma unroll
    for (int r = 0; r < RPB; ++r) {
        float m = sA[r][0];
#pragma unroll
        for (int i = 1; i < 8; ++i) m = fmaxf(m, sA[r][i]);
        M[r] = m;
    }

#pragma unroll
    for (int r = 0; r < RPB; ++r) {
        float s = 0.0f;
        if (wtm[r] >= M[r] - 36.0f) {
            float Mr = M[r];
            float s0 = 0.f, s1 = 0.f, s2 = 0.f, s3 = 0.f;
#pragma unroll
            for (int it = 0; it < 4; ++it) {
                uint4 q = *(const uint4*)(smg + r * 16384 + (it * 256 + tid) * 16);
                float2 g0 = __half22float2(*(const __half2*)&q.x);
                float2 g1 = __half22float2(*(const __half2*)&q.y);
                float2 g2 = __half22float2(*(const __half2*)&q.z);
                float2 g3 = __half22float2(*(const __half2*)&q.w);
                s0 += ex2f_fast(fmaf(g0.x, c1, pp[8 * it + 0]) - Mr);
                s1 += ex2f_fast(fmaf(g0.y, c1, pp[8 * it + 1]) - Mr);
                s2 += ex2f_fast(fmaf(g1.x, c1, pp[8 * it + 2]) - Mr);
                s3 += ex2f_fast(fmaf(g1.y, c1, pp[8 * it + 3]) - Mr);
                s0 += ex2f_fast(fmaf(g2.x, c1, pp[8 * it + 4]) - Mr);
                s1 += ex2f_fast(fmaf(g2.y, c1, pp[8 * it + 5]) - Mr);
                s2 += ex2f_fast(fmaf(g3.x, c1, pp[8 * it + 6]) - Mr);
                s3 += ex2f_fast(fmaf(g3.y, c1, pp[8 * it + 7]) - Mr);
            }
            s = (s0 + s1) + (s2 + s3);
        }
#pragma unroll
        for (int off = 16; off > 0; off >>= 1)
            s += __shfl_xor_sync(0xffffffffu, s, off);
        if (lane == 0) sS[r][wid] = s;
    }
    __syncthreads();

    if (tid < RPB) {
        int r = tid;
        float S = ((sS[r][0] + sS[r][1]) + (sS[r][2] + sS[r][3]))
                + ((sS[r][4] + sS[r][5]) + (sS[r][6] + sS[r][7]));
        const float LOGW = -9.010913347279288f;
        const float LN2  = 0.6931471805599453f;
        float lse = (M[r] + log2f(S)) * LN2;
        float res = -eps * (LOGW + lse);
        if (args.avg[var]) res = 0.5f * (args.oldpot[var][row0 + r] + res);
        args.out[var][row0 + r] = res;
    }
}

// ---------------- snapshot pots + reset ok ----------------
__global__ void snapshot_kernel(const float* p0, const float* p1,
                                const float* p2, const float* p3) {
    const float* p = (blockIdx.x == 0) ? p0 : (blockIdx.x == 1) ? p1
                   : (blockIdx.x == 2) ? p2 : p3;
    for (int i = threadIdx.x; i < NPTS; i += 256)
        d_potref[blockIdx.x][i] = p[i];
    if (threadIdx.x == 0) d_ok[blockIdx.x] = 1;
}

// ---------------- drift check vs snapshot ----------------
__global__ void drift_kernel(const float* p0, const float* p1,
                             const float* p2, const float* p3) {
    const float* p = (blockIdx.x == 0) ? p0 : (blockIdx.x == 1) ? p1
                   : (blockIdx.x == 2) ? p2 : p3;
    __shared__ float sm[256];
    int t = threadIdx.x;
    float d = 0.0f;
    for (int i = t; i < NPTS; i += 256)
        d = fmaxf(d, fabsf(p[i] - d_potref[blockIdx.x][i]));
    sm[t] = d;
    __syncthreads();
    for (int off = 128; off > 0; off >>= 1) {
        if (t < off) sm[t] = fmaxf(sm[t], sm[t + off]);
        __syncthreads();
    }
    if (t == 0) d_ok[blockIdx.x] = (sm[0] <= DRIFT_BUDGET) ? 1 : 0;
}

// ---------------- shortlist build: threshold on u = G + pot ----------------
__global__ void __launch_bounds__(256) build_kernel(SMArgs args) {
    extern __shared__ char smg[];
    const uint32_t smg_u = smem_u32(smg);
    const int var  = blockIdx.y;
    const int row0 = blockIdx.x * RPB;
    const int tid  = threadIdx.x;
    const int lane = tid & 31, wid = tid >> 5;

    const __half* Gbase = args.G[var];
#pragma unroll
    for (int r = 0; r < RPB; ++r) {
        const __half* Gr = Gbase + (size_t)(row0 + r) * NPTS;
#pragma unroll
        for (int q = 0; q < 4; ++q) {
            int idx = q * 256 + tid;
            cp_async16(smg_u + r * 16384 + idx * 16, Gr + idx * 8);
        }
    }
    asm volatile("cp.async.commit_group;" ::: "memory");

    // pot values for this thread's 32 columns (cost domain, no scaling)
    const float* pot = args.pot[var];
    float pc[32];
#pragma unroll
    for (int it = 0; it < 4; ++it) {
        int idx = it * 256 + tid;
        float4 a = ((const float4*)pot)[2 * idx];
        float4 b = ((const float4*)pot)[2 * idx + 1];
        pc[8 * it + 0] = a.x; pc[8 * it + 1] = a.y; pc[8 * it + 2] = a.z; pc[8 * it + 3] = a.w;
        pc[8 * it + 4] = b.x; pc[8 * it + 5] = b.y; pc[8 * it + 6] = b.z; pc[8 * it + 7] = b.w;
    }

    asm volatile("cp.async.wait_group 0;" ::: "memory");
    __syncthreads();

    __shared__ float sA[8];
    __shared__ int   sPfx[256];

    for (int r = 0; r < RPB; ++r) {
        const int row = row0 + r;
        // pass 1: row max of u = G + pot
        float tm = -INFINITY;
#pragma unroll
        for (int it = 0; it < 4; ++it) {
            uint4 q = *(const uint4*)(smg + r * 16384 + (it * 256 + tid) * 16);
            float2 g0 = __half22float2(*(const __half2*)&q.x);
            float2 g1 = __half22float2(*(const __half2*)&q.y);
            float2 g2 = __half22float2(*(const __half2*)&q.z);
            float2 g3 = __half22float2(*(const __half2*)&q.w);
            tm = fmaxf(tm, fmaxf(fmaxf(g0.x + pc[8*it+0], g0.y + pc[8*it+1]),
                                 fmaxf(g1.x + pc[8*it+2], g1.y + pc[8*it+3])));
            tm = fmaxf(tm, fmaxf(fmaxf(g2.x + pc[8*it+4], g2.y + pc[8*it+5]),
                                 fmaxf(g3.x + pc[8*it+6], g3.y + pc[8*it+7])));
        }
#pragma unroll
        for (int off = 16; off > 0; off >>= 1)
            tm = fmaxf(tm, __shfl_xor_sync(0xffffffffu, tm, off));
        if (lane == 0) sA[wid] = tm;
        __syncthreads();
        float maxU = sA[0];
#pragma unroll
        for (int i = 1; i < 8; ++i) maxU = fmaxf(maxU, sA[i]);
        const float thr = maxU - DELTA_BUILD;

        // pass 2: per-thread count
        int cnt = 0;
#pragma unroll
        for (int it = 0; it < 4; ++it) {
            uint4 q = *(const uint4*)(smg + r * 16384 + (it * 256 + tid) * 16);
            const uint32_t w[4] = {q.x, q.y, q.z, q.w};
#pragma unroll
            for (int k = 0; k < 4; ++k) {
                float2 g = __half22float2(*(const __half2*)&w[k]);
                cnt += (g.x + pc[8*it+2*k]   >= thr);
                cnt += (g.y + pc[8*it+2*k+1] >= thr);
            }
        }
        __syncthreads();
        sPfx[tid] = cnt;
        __syncthreads();
        for (int off = 1; off < 256; off <<= 1) {
            int v = (tid >= off) ? sPfx[tid - off] : 0;
            __syncthreads();
            sPfx[tid] += v;
            __syncthreads();
        }
        int excl = sPfx[tid] - cnt;
        int total = sPfx[255];

        // pass 3: write packed entries
        if (total <= CAP) {
            uint32_t* dst = &d_list[var][row][0];
            int o = excl;
#pragma unroll
            for (int it = 0; it < 4; ++it) {
                int chunk = it * 256 + tid;
                uint4 q = *(const uint4*)(smg + r * 16384 + chunk * 16);
                const uint32_t w[4] = {q.x, q.y, q.z, q.w};
                int colb = chunk * 8;
#pragma unroll
                for (int k = 0; k < 4; ++k) {
                    float2 g = __half22float2(*(const __half2*)&w[k]);
                    if (g.x + pc[8*it+2*k]   >= thr)
                        dst[o++] = ((uint32_t)(colb + 2 * k) << 16) | (w[k] & 0xFFFFu);
                    if (g.y + pc[8*it+2*k+1] >= thr)
                        dst[o++] = ((uint32_t)(colb + 2 * k + 1) << 16) | (w[k] >> 16);
                }
            }
        }
        if (tid == 0) d_cnt[var][row] = (total <= CAP) ? total : -1;
        __syncthreads();
    }
}

// ---------------- sparse softmin (eps = 0.0025 launches) ----------------
__global__ void __launch_bounds__(256) softmin4_sparse(SMArgs args, float eps) {
    extern __shared__ char smg[];
    const uint32_t smg_u = smem_u32(smg);
    const int var  = blockIdx.y;
    const int row0 = blockIdx.x * RPB;
    const int tid  = threadIdx.x;
    const int lane = tid & 31, wid = tid >> 5;

    const float L2E = 1.4426950408889634f;
    const float c1 = L2E / eps;
    const float c0 = -c1;
    const int ok = d_ok[var];

    const __half* Gbase = args.G[var];
    const float*  pot   = args.pot[var];

    int  cnt[RPB];
    bool dn[RPB];
#pragma unroll
    for (int r = 0; r < RPB; ++r) {
        int row = row0 + r;
        int c = d_cnt[var][row];
        dn[r] = (!ok) || (c < 0);
        cnt[r] = c;
        if (dn[r]) {
            const __half* Gr = Gbase + (size_t)row * NPTS;
#pragma unroll
            for (int q = 0; q < 4; ++q) {
                int idx = q * 256 + tid;
                cp_async16(smg_u + r * 16384 + idx * 16, Gr + idx * 8);
            }
        } else {
            const uint32_t* Lr = &d_list[var][row][0];
            int nch = (c + 3) >> 2;
            for (int i = tid; i < nch; i += 256)
                cp_async16(smg_u + r * 16384 + i * 16, Lr + i * 4);
        }
    }
    asm volatile("cp.async.commit_group;" ::: "memory");
    asm volatile("cp.async.wait_group 0;" ::: "memory");
    __syncthreads();

    __shared__ float sA[8];

    for (int r = 0; r < RPB; ++r) {
        const int row = row0 + r;
        float tm = -INFINITY;
        if (dn[r]) {
#pragma unroll
            for (int it = 0; it < 4; ++it) {
                int chunk = it * 256 + tid;
                uint4 q = *(const uint4*)(smg + r * 16384 + chunk * 16);
                float4 pa = __ldg((const float4*)(pot + chunk * 8));
                float4 pb = __ldg((const float4*)(pot + chunk * 8 + 4));
                float2 g0 = __half22float2(*(const __half2*)&q.x);
                float2 g1 = __half22float2(*(const __half2*)&q.y);
                float2 g2 = __half22float2(*(const __half2*)&q.z);
                float2 g3 = __half22float2(*(const __half2*)&q.w);
                tm = fmaxf(tm, fmaxf(
                    fmaxf(fmaf(g0.x + pa.x, c1, c0), fmaf(g0.y + pa.y, c1, c0)),
                    fmaxf(fmaf(g1.x + pa.z, c1, c0), fmaf(g1.y + pa.w, c1, c0))));
                tm = fmaxf(tm, fmaxf(
                    fmaxf(fmaf(g2.x + pb.x, c1, c0), fmaf(g2.y + pb.y, c1, c0)),
                    fmaxf(fmaf(g3.x + pb.z, c1, c0), fmaf(g3.y + pb.w, c1, c0))));
            }
        } else {
            for (int e = tid; e < cnt[r]; e += 256) {
                uint32_t p = *(const uint32_t*)(smg + r * 16384 + e * 4);
                float g = __half2float(__ushort_as_half((unsigned short)(p & 0xFFFFu)));
                tm = fmaxf(tm, fmaf(g + __ldg(pot + (p >> 16)), c1, c0));
            }
        }
#pragma unroll
        for (int off = 16; off > 0; off >>= 1)
            tm = fmaxf(tm, __shfl_xor_sync(0xffffffffu, tm, off));
        float wtm = tm;
        if (lane == 0) sA[wid] = tm;
        __syncthreads();
        float M = sA[0];
#pragma unroll
        for (int i = 1; i < 8; ++i) M = fmaxf(M, sA[i]);
        __syncthreads();

        float s = 0.0f;
        if (dn[r]) {
            if (wtm >= M - 40.0f) {
                float s0 = 0.f, s1 = 0.f;
#pragma unroll
                for (int it = 0; it < 4; ++it) {
                    int chunk = it * 256 + tid;
                    uint4 q = *(const uint4*)(smg + r * 16384 + chunk * 16);
                    float4 pa = __ldg((const float4*)(pot + chunk * 8));
                    float4 pb = __ldg((const float4*)(pot + chunk * 8 + 4));
                    float2 g0 = __half22float2(*(const __half2*)&q.x);
                    float2 g1 = __half22float2(*(const __half2*)&q.y);
                    float2 g2 = __half22float2(*(const __half2*)&q.z);
                    float2 g3 = __half22float2(*(const __half2*)&q.w);
                    s0 += ex2f_fast(fmaf(g0.x + pa.x, c1, c0) - M);
                    s1 += ex2f_fast(fmaf(g0.y + pa.y, c1, c0) - M);
                    s0 += ex2f_fast(fmaf(g1.x + pa.z, c1, c0) - M);
                    s1 += ex2f_fast(fmaf(g1.y + pa.w, c1, c0) - M);
                    s0 += ex2f_fast(fmaf(g2.x + pb.x, c1, c0) - M);
                    s1 += ex2f_fast(fmaf(g2.y + pb.y, c1, c0) - M);
                    s0 += ex2f_fast(fmaf(g3.x + pb.z, c1, c0) - M);
                    s1 += ex2f_fast(fmaf(g3.y + pb.w, c1, c0) - M);
                }
                s = s0 + s1;
            }
        } else {
            for (int e = tid; e < cnt[r]; e += 256) {
                uint32_t p = *(const uint32_t*)(smg + r * 16384 + e * 4);
                float g = __half2float(__ushort_as_half((unsigned short)(p & 0xFFFFu)));
                s += ex2f_fast(fmaf(g + __ldg(pot + (p >> 16)), c1, c0) - M);
            }
        }
#pragma unroll
        for (int off = 16; off > 0; off >>= 1)
            s += __shfl_xor_sync(0xffffffffu, s, off);
        if (lane == 0) sA[wid] = s;
        __syncthreads();
        if (tid == 0) {
            float S = ((sA[0] + sA[1]) + (sA[2] + sA[3]))
                    + ((sA[4] + sA[5]) + (sA[6] + sA[7]));
            const float LOGW = -9.010913347279288f;
            const float LN2  = 0.6931471805599453f;
            float lse = (M + log2f(S)) * LN2;
            float res = -eps * (LOGW + lse);
            if (args.avg[var]) res = 0.5f * (args.oldpot[var][row] + res);
            args.out[var][row] = res;
        }
        __syncthreads();
    }
}

// ---------------- final reduction ----------------
__global__ void final_reduce(float* __restrict__ out) {
    __shared__ float sh[1024];
    int t = threadIdx.x;
    float s = 0.0f;
    for (int i = t; i < NPTS; i += 1024)
        s += (d_ffin[i] - d_xfin[i]) + (d_gfin[i] - d_yfin[i]);
    sh[t] = s;
    __syncthreads();
    for (int off = 512; off > 0; off >>= 1) {
        if (t < off) sh[t] += sh[t + off];
        __syncthreads();
    }
    if (t == 0) out[0] = sh[0] / (float)NPTS;
}

// ---------------- host ----------------
static void* symaddr(const void* sym) {
    void* p = nullptr;
    cudaGetSymbolAddress(&p, sym);
    return p;
}

extern "C" void kernel_launch(void* const* d_in, const int* in_sizes, int n_in,
                              void* d_out, int out_size) {
    const float* x1 = (const float*)d_in[0];
    const float* x2 = (const float*)d_in[1];
    const float* w  = (const float*)d_in[2];

    __half* an  = (__half*)symaddr(d_anh);
    __half* bn  = (__half*)symaddr(d_bnh);
    __half* Gxy = (__half*)symaddr(d_Gxy);
    __half* Gyx = (__half*)symaddr(d_Gyx);
    __half* Gxx = (__half*)symaddr(d_Gxx);
    __half* Gyy = (__half*)symaddr(d_Gyy);
    float* fb  = (float*)symaddr(d_f);
    float* gb  = (float*)symaddr(d_g);
    float* xb  = (float*)symaddr(d_fxx);
    float* yb  = (float*)symaddr(d_gyy);
    float* ffin = (float*)symaddr(d_ffin);
    float* gfin = (float*)symaddr(d_gfin);
    float* xfin = (float*)symaddr(d_xfin);
    float* yfin = (float*)symaddr(d_yfin);

    cudaFuncSetAttribute(gemm_mma, cudaFuncAttributeMaxDynamicSharedMemorySize, GEMM_SMEM);
    cudaFuncSetAttribute(softmin4, cudaFuncAttributeMaxDynamicSharedMemorySize, SM_SOFTMIN);
    cudaFuncSetAttribute(build_kernel, cudaFuncAttributeMaxDynamicSharedMemorySize, SM_SOFTMIN);
    cudaFuncSetAttribute(softmin4_sparse, cudaFuncAttributeMaxDynamicSharedMemorySize, SM_SOFTMIN);

    wprep_kernel<<<1, DIM>>>(w);
    rownorm_kernel<<<2 * NPTS, DIM>>>(x1, x2);
    zero_kernel<<<NPTS / 256, 256>>>();

    {
        GArgs ga;
        ga.A[0] = an; ga.B[0] = bn; ga.C[0] = Gxy; ga.CT[0] = Gyx; ga.sym[0] = 0;
        ga.A[1] = an; ga.B[1] = an; ga.C[1] = Gxx; ga.CT[1] = Gxx; ga.sym[1] = 1;
        ga.A[2] = bn; ga.B[2] = bn; ga.C[2] = Gyy; ga.CT[2] = Gyy; ga.sym[2] = 1;
        gemm_mma<<<dim3(NPTS / 128, NPTS / 128, 3), 256, GEMM_SMEM>>>(ga);
    }

    const float eps_list[10] = {4.0f, 1.0f, 0.25f, 0.0625f, 0.015625f,
                                0.00390625f, EPS_F, EPS_F, EPS_F, EPS_F};
    dim3 sgrid(NPTS / RPB, 4);
    int cur = 0;

    // iterations 0..5: dense
    for (int i = 0; i < 6; ++i) {
        int nxt = 1 - cur;
        SMArgs a;
        a.G[0] = Gxx;  a.pot[0] = xb + cur * NPTS; a.oldpot[0] = xb + cur * NPTS; a.out[0] = xb + nxt * NPTS; a.avg[0] = 1;
        a.G[1] = Gyy;  a.pot[1] = yb + cur * NPTS; a.oldpot[1] = yb + cur * NPTS; a.out[1] = yb + nxt * NPTS; a.avg[1] = 1;
        a.G[2] = Gxy;  a.pot[2] = gb + cur * NPTS; a.oldpot[2] = nullptr;         a.out[2] = fb + nxt * NPTS; a.avg[2] = 0;
        a.G[3] = Gyx;  a.pot[3] = fb + cur * NPTS; a.oldpot[3] = nullptr;         a.out[3] = gb + nxt * NPTS; a.avg[3] = 0;
        softmin4<<<sgrid, 256, SM_SOFTMIN>>>(a, eps_list[i]);
        cur = nxt;
    }

    // snapshot + build shortlists on u = G + pot (pots entering iteration 6)
    snapshot_kernel<<<4, 256>>>(xb + cur * NPTS, yb + cur * NPTS,
                                gb + cur * NPTS, fb + cur * NPTS);
    {
        SMArgs b;
        b.G[0] = Gxx; b.pot[0] = xb + cur * NPTS;
        b.G[1] = Gyy; b.pot[1] = yb + cur * NPTS;
        b.G[2] = Gxy; b.pot[2] = gb + cur * NPTS;
        b.G[3] = Gyx; b.pot[3] = fb + cur * NPTS;
        b.oldpot[0] = b.oldpot[1] = b.oldpot[2] = b.oldpot[3] = nullptr;
        b.out[0] = b.out[1] = b.out[2] = b.out[3] = nullptr;
        b.avg[0] = b.avg[1] = b.avg[2] = b.avg[3] = 0;
        build_kernel<<<sgrid, 256, SM_SOFTMIN>>>(b);
    }

    // iterations 6..9: sparse with drift guard
    for (int i = 6; i < 10; ++i) {
        int nxt = 1 - cur;
        SMArgs a;
        a.G[0] = Gxx;  a.pot[0] = xb + cur * NPTS; a.oldpot[0] = xb + cur * NPTS; a.out[0] = xb + nxt * NPTS; a.avg[0] = 1;
        a.G[1] = Gyy;  a.pot[1] = yb + cur * NPTS; a.oldpot[1] = yb + cur * NPTS; a.out[1] = yb + nxt * NPTS; a.avg[1] = 1;
        a.G[2] = Gxy;  a.pot[2] = gb + cur * NPTS; a.oldpot[2] = nullptr;         a.out[2] = fb + nxt * NPTS; a.avg[2] = 0;
        a.G[3] = Gyx;  a.pot[3] = fb + cur * NPTS; a.oldpot[3] = nullptr;         a.out[3] = gb + nxt * NPTS; a.avg[3] = 0;
        drift_kernel<<<4, 256>>>(a.pot[0], a.pot[1], a.pot[2], a.pot[3]);
        softmin4_sparse<<<sgrid, 256, SM_SOFTMIN>>>(a, eps_list[i]);
        cur = nxt;
    }

    // final extrapolation (variant mapping identical to build)
    {
        SMArgs a;
        a.G[0] = Gxx; a.pot[0] = xb + cur * NPTS; a.oldpot[0] = nullptr; a.out[0] = xfin; a.avg[0] = 0;
        a.G[1] = Gyy; a.pot[1] = yb + cur * NPTS; a.oldpot[1] = nullptr; a.out[1] = yfin; a.avg[1] = 0;
        a.G[2] = Gxy; a.pot[2] = gb + cur * NPTS; a.oldpot[2] = nullptr; a.out[2] = ffin; a.avg[2] = 0;
        a.G[3] = Gyx; a.pot[3] = fb + cur * NPTS; a.oldpot[3] = nullptr; a.out[3] = gfin; a.avg[3] = 0;
        drift_kernel<<<4, 256>>>(a.pot[0], a.pot[1], a.pot[2], a.pot[3]);
        softmin4_sparse<<<sgrid, 256, SM_SOFTMIN>>>(a, EPS_F);
    }

    final_reduce<<<1, 1024>>>((float*)d_out);
}

// round 15
// speedup vs baseline: 1.4708x; 1.4708x over previous
#include <cuda_runtime.h>
#include <cuda_fp16.h>
#include <math.h>
#include <stdint.h>

#define NPTS 8192
#define DIM 256
#define KC 64
#define NCHUNK (DIM / KC)
#define RPB 4
#define RPB8 8
#define SM_SOFTMIN 65536
#define GEMM_SMEM 65536
#define FP8_SCALE 16.0f

// ---------------- static device scratch (no allocation allowed) ----------------
__device__ float   d_wc[DIM];
__device__ __half  d_anh[(size_t)NPTS * DIM];
__device__ __half  d_bnh[(size_t)NPTS * DIM];
__device__ __half  d_Gxy[(size_t)NPTS * NPTS];
__device__ __half  d_Gyx[(size_t)NPTS * NPTS];
__device__ __half  d_Gxx[(size_t)NPTS * NPTS];
__device__ __half  d_Gyy[(size_t)NPTS * NPTS];
__device__ uint8_t d_Gxy8[(size_t)NPTS * NPTS];   // e4m3, scaled x16
__device__ uint8_t d_Gyx8[(size_t)NPTS * NPTS];
__device__ uint8_t d_Gxx8[(size_t)NPTS * NPTS];
__device__ uint8_t d_Gyy8[(size_t)NPTS * NPTS];
__device__ float   d_f[2][NPTS];
__device__ float   d_g[2][NPTS];
__device__ float   d_fxx[2][NPTS];
__device__ float   d_gyy[2][NPTS];
__device__ float   d_ffin[NPTS], d_gfin[NPTS], d_xfin[NPTS], d_yfin[NPTS];

__device__ __forceinline__ float ex2f_fast(float x) {
    float y; asm("ex2.approx.ftz.f32 %0, %1;" : "=f"(y) : "f"(x)); return y;
}
__device__ __forceinline__ uint32_t smem_u32(const void* p) {
    uint32_t a;
    asm("{ .reg .u64 t; cvta.to.shared.u64 t, %1; cvt.u32.u64 %0, t; }" : "=r"(a) : "l"(p));
    return a;
}
__device__ __forceinline__ void cp_async16(uint32_t dst, const void* src) {
    asm volatile("cp.async.cg.shared.global [%0], [%1], 16;" :: "r"(dst), "l"(src) : "memory");
}
__device__ __forceinline__ __half2 e4m3x2_to_h2(uint16_t v) {
    uint32_t r;
    asm("cvt.rn.f16x2.e4m3x2 %0, %1;" : "=r"(r) : "h"(v));
    return *(__half2*)&r;
}
__device__ __forceinline__ uint16_t h2_to_e4m3x2(uint32_t h2bits) {
    __half2 h = *(__half2*)&h2bits;
    h = __hmul2(h, __floats2half2_rn(FP8_SCALE, FP8_SCALE));
    uint16_t r;
    asm("cvt.rn.satfinite.e4m3x2.f16x2 %0, %1;" : "=h"(r) : "r"(*(uint32_t*)&h));
    return r;
}
#define LDMX4(r, addr)                                                          \
    asm volatile("ldmatrix.sync.aligned.m8n8.x4.shared.b16 {%0,%1,%2,%3}, [%4];" \
                 : "=r"((r)[0]), "=r"((r)[1]), "=r"((r)[2]), "=r"((r)[3])        \
                 : "r"(addr))

// ---------------- prep ----------------
__global__ void wprep_kernel(const float* __restrict__ w) {
    __shared__ float sh[DIM];
    int t = threadIdx.x;
    float c = fminf(fmaxf(w[t], 0.0f), 2.0f);
    sh[t] = c;
    __syncthreads();
    for (int off = DIM / 2; off > 0; off >>= 1) {
        if (t < off) sh[t] += sh[t + off];
        __syncthreads();
    }
    d_wc[t] = c * ((float)DIM / sh[0]);
}

__global__ void rownorm_kernel(const float* __restrict__ x1, const float* __restrict__ x2) {
    __shared__ float sh[DIM];
    int b = blockIdx.x, t = threadIdx.x;
    float v;
    if (b < NPTS) v = d_wc[t] * x1[(size_t)b * DIM + t];
    else          v = x2[(size_t)(b - NPTS) * DIM + t];
    sh[t] = v * v;
    __syncthreads();
    for (int off = DIM / 2; off > 0; off >>= 1) {
        if (t < off) sh[t] += sh[t + off];
        __syncthreads();
    }
    float inv = 1.0f / (sqrtf(sh[0]) + 1e-12f);
    __half h = __float2half_rn(v * inv);
    if (b < NPTS) d_anh[(size_t)b * DIM + t] = h;
    else          d_bnh[(size_t)(b - NPTS) * DIM + t] = h;
}

__global__ void zero_kernel() {
    int i = blockIdx.x * blockDim.x + threadIdx.x;
    if (i < NPTS) {
        d_f[0][i] = 0.0f; d_g[0][i] = 0.0f;
        d_fxx[0][i] = 0.0f; d_gyy[0][i] = 0.0f;
    }
}

// ---------------- HMMA GEMM: 3 problems, fp16 + fp8 outputs ----------------
struct GArgs {
    const __half* A[3];
    const __half* B[3];
    __half*       C[3];
    __half*       CT[3];
    uint8_t*      C8[3];
    uint8_t*      CT8[3];
    int           sym[3];
};

__global__ void __launch_bounds__(256, 2) gemm_mma(GArgs ga) {
    extern __shared__ char smem[];
    const int prob = blockIdx.z;
    const int btx = blockIdx.x, bty = blockIdx.y;
    const int sym = ga.sym[prob];
    if (sym && btx > bty) return;
    const __half* A   = ga.A[prob];
    const __half* B   = ga.B[prob];
    __half*       C   = ga.C[prob];
    __half*       CT  = ga.CT[prob];
    uint8_t*      C8  = ga.C8[prob];
    uint8_t*      CT8 = ga.CT8[prob];

    const uint32_t smem_base = smem_u32(smem);
    const int tid = threadIdx.x;
    const int wid = tid >> 5, lane = tid & 31;
    const int warp_m = wid >> 2, warp_n = wid & 3;
    const int rowBase = bty * 128;
    const int colBase = btx * 128;

    const int mat = lane >> 3, rin = lane & 7;
    const int a_row_in = (mat & 1) * 8 + rin;
    const int a_kh     = (mat >> 1) * 8;
    const int b_row_in = (mat >> 1) * 8 + rin;
    const int b_kh     = (mat & 1) * 8;

    float acc[4][4][4];
#pragma unroll
    for (int mi = 0; mi < 4; ++mi)
#pragma unroll
        for (int ni = 0; ni < 4; ++ni)
#pragma unroll
            for (int q = 0; q < 4; ++q) acc[mi][ni][q] = 0.0f;

#define ISSUE_CHUNK(c, b) do {                                                  \
        const __half* Asrc_ = A + (size_t)rowBase * DIM + (c) * KC;             \
        const __half* Bsrc_ = B + (size_t)colBase * DIM + (c) * KC;             \
        uint32_t Ab_ = smem_base + (b) * 32768;                                 \
        uint32_t Bb_ = Ab_ + 16384;                                             \
        _Pragma("unroll")                                                       \
        for (int q_ = 0; q_ < 4; ++q_) {                                        \
            int i_ = q_ * 256 + tid;                                            \
            int r_ = i_ >> 3, cw_ = i_ & 7;                                     \
            uint32_t off_ = r_ * 128 + (((uint32_t)(cw_ ^ (r_ & 7))) << 4);     \
            cp_async16(Ab_ + off_, Asrc_ + (size_t)r_ * DIM + cw_ * 8);         \
            cp_async16(Bb_ + off_, Bsrc_ + (size_t)r_ * DIM + cw_ * 8);         \
        }                                                                       \
        asm volatile("cp.async.commit_group;" ::: "memory");                    \
    } while (0)

    ISSUE_CHUNK(0, 0);
#pragma unroll
    for (int c = 0; c < NCHUNK; ++c) {
        if (c + 1 < NCHUNK) {
            ISSUE_CHUNK(c + 1, (c + 1) & 1);
            asm volatile("cp.async.wait_group 1;" ::: "memory");
        } else {
            asm volatile("cp.async.wait_group 0;" ::: "memory");
        }
        __syncthreads();
        uint32_t Ab = smem_base + (c & 1) * 32768;
        uint32_t Bb = Ab + 16384;
#pragma unroll
        for (int ks = 0; ks < 4; ++ks) {
            uint32_t bf[2][4];
#pragma unroll
            for (int p = 0; p < 2; ++p) {
                int nrow = warp_n * 32 + p * 16 + b_row_in;
                int kcol = ks * 16 + b_kh;
                uint32_t addr = Bb + nrow * 128 + ((uint32_t)((kcol >> 3) ^ (nrow & 7)) << 4);
                LDMX4(bf[p], addr);
            }
#pragma unroll
            for (int mi = 0; mi < 4; ++mi) {
                uint32_t af[4];
                int arow = warp_m * 64 + mi * 16 + a_row_in;
                int kcol = ks * 16 + a_kh;
                uint32_t addr = Ab + arow * 128 + ((uint32_t)((kcol >> 3) ^ (arow & 7)) << 4);
                LDMX4(af, addr);
#pragma unroll
                for (int ni = 0; ni < 4; ++ni) {
                    asm volatile(
                        "mma.sync.aligned.m16n8k16.row.col.f32.f16.f16.f32 "
                        "{%0,%1,%2,%3}, {%4,%5,%6,%7}, {%8,%9}, {%0,%1,%2,%3};"
                        : "+f"(acc[mi][ni][0]), "+f"(acc[mi][ni][1]),
                          "+f"(acc[mi][ni][2]), "+f"(acc[mi][ni][3])
                        : "r"(af[0]), "r"(af[1]), "r"(af[2]), "r"(af[3]),
                          "r"(bf[ni >> 1][(ni & 1) * 2]), "r"(bf[ni >> 1][(ni & 1) * 2 + 1]));
                }
            }
        }
        __syncthreads();
    }
#undef ISSUE_CHUNK

    __half* stage = (__half*)smem;
#pragma unroll
    for (int mi = 0; mi < 4; ++mi)
#pragma unroll
        for (int ni = 0; ni < 4; ++ni) {
            int row = warp_m * 64 + mi * 16 + (lane >> 2);
            int col = warp_n * 32 + ni * 8 + 2 * (lane & 3);
            __half2 lo = __floats2half2_rn(acc[mi][ni][0], acc[mi][ni][1]);
            __half2 hi = __floats2half2_rn(acc[mi][ni][2], acc[mi][ni][3]);
            *(__half2*)(stage + row * 136 + col)       = lo;
            *(__half2*)(stage + (row + 8) * 136 + col) = hi;
        }
    __syncthreads();
#pragma unroll
    for (int i = tid; i < 2048; i += 256) {
        int r = i >> 4, ch = i & 15;
        uint4 v = *(uint4*)(stage + r * 136 + ch * 8);
        *(uint4*)(C + (size_t)(rowBase + r) * NPTS + colBase + ch * 8) = v;
        // fp8 copy (scaled x16)
        uint16_t b0 = h2_to_e4m3x2(v.x);
        uint16_t b1 = h2_to_e4m3x2(v.y);
        uint16_t b2 = h2_to_e4m3x2(v.z);
        uint16_t b3 = h2_to_e4m3x2(v.w);
        uint2 pk;
        pk.x = (uint32_t)b0 | ((uint32_t)b1 << 16);
        pk.y = (uint32_t)b2 | ((uint32_t)b3 << 16);
        *(uint2*)(C8 + (size_t)(rowBase + r) * NPTS + colBase + ch * 8) = pk;
    }

    if (!(sym && btx == bty)) {
        __syncthreads();
#pragma unroll
        for (int mi = 0; mi < 4; ++mi)
#pragma unroll
            for (int ni = 0; ni < 4; ++ni) {
                int row = warp_m * 64 + mi * 16 + (lane >> 2);
                int col = warp_n * 32 + ni * 8 + 2 * (lane & 3);
                stage[col * 136 + row]           = __float2half_rn(acc[mi][ni][0]);
                stage[(col + 1) * 136 + row]     = __float2half_rn(acc[mi][ni][1]);
                stage[col * 136 + row + 8]       = __float2half_rn(acc[mi][ni][2]);
                stage[(col + 1) * 136 + row + 8] = __float2half_rn(acc[mi][ni][3]);
            }
        __syncthreads();
#pragma unroll
        for (int i = tid; i < 2048; i += 256) {
            int r = i >> 4, ch = i & 15;
            uint4 v = *(uint4*)(stage + r * 136 + ch * 8);
            *(uint4*)(CT + (size_t)(colBase + r) * NPTS + rowBase + ch * 8) = v;
            uint16_t b0 = h2_to_e4m3x2(v.x);
            uint16_t b1 = h2_to_e4m3x2(v.y);
            uint16_t b2 = h2_to_e4m3x2(v.z);
            uint16_t b3 = h2_to_e4m3x2(v.w);
            uint2 pk;
            pk.x = (uint32_t)b0 | ((uint32_t)b1 << 16);
            pk.y = (uint32_t)b2 | ((uint32_t)b3 << 16);
            *(uint2*)(CT8 + (size_t)(colBase + r) * NPTS + rowBase + ch * 8) = pk;
        }
    }
}

// ---------------- dense softmin fp16 (R12 proven) ----------------
struct SMArgs {
    const __half* G[4];
    const float*  pot[4];
    const float*  oldpot[4];
    float*        out[4];
    int           avg[4];
};

__global__ void __launch_bounds__(256, 3) softmin4(SMArgs args, float eps) {
    extern __shared__ char smg[];
    const uint32_t smg_u = smem_u32(smg);
    const int var  = blockIdx.y;
    const int row0 = blockIdx.x * RPB;
    const int tid  = threadIdx.x;
    const int lane = tid & 31, wid = tid >> 5;

    const float L2E = 1.4426950408889634f;
    const float c1 = L2E / eps;
    const float c0 = -c1;

    const __half* Gbase = args.G[var];
#pragma unroll
    for (int r = 0; r < RPB; ++r) {
        const __half* Gr = Gbase + (size_t)(row0 + r) * NPTS;
#pragma unroll
        for (int q = 0; q < 4; ++q) {
            int idx = q * 256 + tid;
            cp_async16(smg_u + r * 16384 + idx * 16, Gr + idx * 8);
        }
    }
    asm volatile("cp.async.commit_group;" ::: "memory");

    const float* pot = args.pot[var];
    float pp[32];
#pragma unroll
    for (int it = 0; it < 4; ++it) {
        int idx = it * 256 + tid;
        float4 a = ((const float4*)pot)[2 * idx];
        float4 b = ((const float4*)pot)[2 * idx + 1];
        pp[8 * it + 0] = fmaf(a.x, c1, c0); pp[8 * it + 1] = fmaf(a.y, c1, c0);
        pp[8 * it + 2] = fmaf(a.z, c1, c0); pp[8 * it + 3] = fmaf(a.w, c1, c0);
        pp[8 * it + 4] = fmaf(b.x, c1, c0); pp[8 * it + 5] = fmaf(b.y, c1, c0);
        pp[8 * it + 6] = fmaf(b.z, c1, c0); pp[8 * it + 7] = fmaf(b.w, c1, c0);
    }
    __half2 pph2[16];
#pragma unroll
    for (int j = 0; j < 16; ++j)
        pph2[j] = __floats2half2_rn(pp[2 * j], pp[2 * j + 1]);
    const __half2 c1h2 = __floats2half2_rn(c1, c1);

    asm volatile("cp.async.wait_group 0;" ::: "memory");

    __shared__ float sA[RPB][8];
    __shared__ float sS[RPB][8];

    float wtm[RPB];
#pragma unroll
    for (int r = 0; r < RPB; ++r) {
        __half2 mh = __floats2half2_rn(-60000.0f, -60000.0f);
#pragma unroll
        for (int it = 0; it < 4; ++it) {
            uint4 q = *(const uint4*)(smg + r * 16384 + (it * 256 + tid) * 16);
            const __half2* g2 = (const __half2*)&q;
#pragma unroll
            for (int k = 0; k < 4; ++k)
                mh = __hmax2(mh, __hfma2(g2[k], c1h2, pph2[it * 4 + k]));
        }
        float2 mf = __half22float2(mh);
        float tm = fmaxf(mf.x, mf.y);
#pragma unroll
        for (int off = 16; off > 0; off >>= 1)
            tm = fmaxf(tm, __shfl_xor_sync(0xffffffffu, tm, off));
        wtm[r] = tm;
        if (lane == 0) sA[r][wid] = tm;
    }
    __syncthreads();
    float M[RPB];
#pragma unroll
    for (int r = 0; r < RPB; ++r) {
        float m = sA[r][0];
#pragma unroll
        for (int i = 1; i < 8; ++i) m = fmaxf(m, sA[r][i]);
        M[r] = m;
    }

#pragma unroll
    for (int r = 0; r < RPB; ++r) {
        float s = 0.0f;
        if (wtm[r] >= M[r] - 36.0f) {
            float Mr = M[r];
            float s0 = 0.f, s1 = 0.f, s2 = 0.f, s3 = 0.f;
#pragma unroll
            for (int it = 0; it < 4; ++it) {
                uint4 q = *(const uint4*)(smg + r * 16384 + (it * 256 + tid) * 16);
                float2 g0 = __half22float2(*(const __half2*)&q.x);
                float2 g1 = __half22float2(*(const __half2*)&q.y);
                float2 g2 = __half22float2(*(const __half2*)&q.z);
                float2 g3 = __half22float2(*(const __half2*)&q.w);
                s0 += ex2f_fast(fmaf(g0.x, c1, pp[8 * it + 0]) - Mr);
                s1 += ex2f_fast(fmaf(g0.y, c1, pp[8 * it + 1]) - Mr);
                s2 += ex2f_fast(fmaf(g1.x, c1, pp[8 * it + 2]) - Mr);
                s3 += ex2f_fast(fmaf(g1.y, c1, pp[8 * it + 3]) - Mr);
                s0 += ex2f_fast(fmaf(g2.x, c1, pp[8 * it + 4]) - Mr);
                s1 += ex2f_fast(fmaf(g2.y, c1, pp[8 * it + 5]) - Mr);
                s2 += ex2f_fast(fmaf(g3.x, c1, pp[8 * it + 6]) - Mr);
                s3 += ex2f_fast(fmaf(g3.y, c1, pp[8 * it + 7]) - Mr);
            }
            s = (s0 + s1) + (s2 + s3);
        }
#pragma unroll
        for (int off = 16; off > 0; off >>= 1)
            s += __shfl_xor_sync(0xffffffffu, s, off);
        if (lane == 0) sS[r][wid] = s;
    }
    __syncthreads();

    if (tid < RPB) {
        int r = tid;
        float S = ((sS[r][0] + sS[r][1]) + (sS[r][2] + sS[r][3]))
                + ((sS[r][4] + sS[r][5]) + (sS[r][6] + sS[r][7]));
        const float LOGW = -9.010913347279288f;
        const float LN2  = 0.6931471805599453f;
        float lse = (M[r] + log2f(S)) * LN2;
        float res = -eps * (LOGW + lse);
        if (args.avg[var]) res = 0.5f * (args.oldpot[var][row0 + r] + res);
        args.out[var][row0 + r] = res;
    }
}

// ---------------- dense softmin fp8 (iters with eps >= sigma) ----------------
// Ĝ = 16*G stored as e4m3; u = Ĝ*(c1/16) + (pot-1)*c1.
struct SM8Args {
    const uint8_t* G[4];
    const float*   pot[4];
    const float*   oldpot[4];
    float*         out[4];
    int            avg[4];
};

__global__ void __launch_bounds__(256, 3) softmin8(SM8Args args, float eps) {
    extern __shared__ char smg[];               // RPB8 * 8 KB = 64 KB
    const uint32_t smg_u = smem_u32(smg);
    const int var  = blockIdx.y;
    const int row0 = blockIdx.x * RPB8;
    const int tid  = threadIdx.x;
    const int lane = tid & 31, wid = tid >> 5;

    const float L2E = 1.4426950408889634f;
    const float c1  = L2E / eps;
    const float c0  = -c1;
    const float c1g = c1 / FP8_SCALE;

    const uint8_t* Gbase = args.G[var];
#pragma unroll
    for (int r = 0; r < RPB8; ++r) {
        const uint8_t* Gr = Gbase + (size_t)(row0 + r) * NPTS;
#pragma unroll
        for (int q = 0; q < 2; ++q) {
            int idx = q * 256 + tid;            // 0..511 16B chunks
            cp_async16(smg_u + r * 8192 + idx * 16, Gr + idx * 16);
        }
    }
    asm volatile("cp.async.commit_group;" ::: "memory");

    // pot fold for this thread's 32 columns: chunk q covers cols q*4096 + tid*16 .. +15
    const float* pot = args.pot[var];
    float pp[32];
#pragma unroll
    for (int q = 0; q < 2; ++q) {
        int cbase = q * 4096 + tid * 16;
#pragma unroll
        for (int e4 = 0; e4 < 4; ++e4) {
            float4 a = *(const float4*)(pot + cbase + e4 * 4);
            pp[q * 16 + e4 * 4 + 0] = fmaf(a.x, c1, c0);
            pp[q * 16 + e4 * 4 + 1] = fmaf(a.y, c1, c0);
            pp[q * 16 + e4 * 4 + 2] = fmaf(a.z, c1, c0);
            pp[q * 16 + e4 * 4 + 3] = fmaf(a.w, c1, c0);
        }
    }
    __half2 pph2[16];
#pragma unroll
    for (int j = 0; j < 16; ++j)
        pph2[j] = __floats2half2_rn(pp[2 * j], pp[2 * j + 1]);
    const __half2 cgh2 = __floats2half2_rn(c1g, c1g);

    asm volatile("cp.async.wait_group 0;" ::: "memory");

    __shared__ float sA[RPB8][8];
    __shared__ float sS[RPB8][8];

    // pass A: half2 max
    float wtm[RPB8];
#pragma unroll
    for (int r = 0; r < RPB8; ++r) {
        __half2 mh = __floats2half2_rn(-60000.0f, -60000.0f);
#pragma unroll
        for (int q = 0; q < 2; ++q) {
            uint4 v = *(const uint4*)(smg + r * 8192 + (q * 256 + tid) * 16);
            const uint32_t w[4] = {v.x, v.y, v.z, v.w};
#pragma unroll
            for (int k = 0; k < 4; ++k) {
                __half2 ha = e4m3x2_to_h2((uint16_t)(w[k] & 0xFFFFu));
                __half2 hb = e4m3x2_to_h2((uint16_t)(w[k] >> 16));
                mh = __hmax2(mh, __hfma2(ha, cgh2, pph2[q * 8 + 2 * k]));
                mh = __hmax2(mh, __hfma2(hb, cgh2, pph2[q * 8 + 2 * k + 1]));
            }
        }
        float2 mf = __half22float2(mh);
        float tm = fmaxf(mf.x, mf.y);
#pragma unroll
        for (int off = 16; off > 0; off >>= 1)
            tm = fmaxf(tm, __shfl_xor_sync(0xffffffffu, tm, off));
        wtm[r] = tm;
        if (lane == 0) sA[r][wid] = tm;
    }
    __syncthreads();
    float M[RPB8];
#pragma unroll
    for (int r = 0; r < RPB8; ++r) {
        float m = sA[r][0];
#pragma unroll
        for (int i = 1; i < 8; ++i) m = fmaxf(m, sA[r][i]);
        M[r] = m;
    }

    // pass B: fp32 exp-sum, contributing warps only
#pragma unroll
    for (int r = 0; r < RPB8; ++r) {
        float s = 0.0f;
        if (wtm[r] >= M[r] - 36.0f) {
            float Mr = M[r];
            float s0 = 0.f, s1 = 0.f;
#pragma unroll
            for (int q = 0; q < 2; ++q) {
                uint4 v = *(const uint4*)(smg + r * 8192 + (q * 256 + tid) * 16);
                const uint32_t w[4] = {v.x, v.y, v.z, v.w};
#pragma unroll
                for (int k = 0; k < 4; ++k) {
                    float2 ga = __half22float2(e4m3x2_to_h2((uint16_t)(w[k] & 0xFFFFu)));
                    float2 gb = __half22float2(e4m3x2_to_h2((uint16_t)(w[k] >> 16)));
                    s0 += ex2f_fast(fmaf(ga.x, c1g, pp[q * 16 + 4 * k + 0]) - Mr);
                    s1 += ex2f_fast(fmaf(ga.y, c1g, pp[q * 16 + 4 * k + 1]) - Mr);
                    s0 += ex2f_fast(fmaf(gb.x, c1g, pp[q * 16 + 4 * k + 2]) - Mr);
                    s1 += ex2f_fast(fmaf(gb.y, c1g, pp[q * 16 + 4 * k + 3]) - Mr);
                }
            }
            s = s0 + s1;
        }
#pragma unroll
        for (int off = 16; off > 0; off >>= 1)
            s += __shfl_xor_sync(0xffffffffu, s, off);
        if (lane == 0) sS[r][wid] = s;
    }
    __syncthreads();

    if (tid < RPB8) {
        int r = tid;
        float S = ((sS[r][0] + sS[r][1]) + (sS[r][2] + sS[r][3]))
                + ((sS[r][4] + sS[r][5]) + (sS[r][6] + sS[r][7]));
        const float LOGW = -9.010913347279288f;
        const float LN2  = 0.6931471805599453f;
        float lse = (M[r] + log2f(S)) * LN2;
        float res = -eps * (LOGW + lse);
        if (args.avg[var]) res = 0.5f * (args.oldpot[var][row0 + r] + res);
        args.out[var][row0 + r] = res;
    }
}

// ---------------- final reduction ----------------
__global__ void final_reduce(float* __restrict__ out) {
    __shared__ float sh[1024];
    int t = threadIdx.x;
    float s = 0.0f;
    for (int i = t; i < NPTS; i += 1024)
        s += (d_ffin[i] - d_xfin[i]) + (d_gfin[i] - d_yfin[i]);
    sh[t] = s;
    __syncthreads();
    for (int off = 512; off > 0; off >>= 1) {
        if (t < off) sh[t] += sh[t + off];
        __syncthreads();
    }
    if (t == 0) out[0] = sh[0] / (float)NPTS;
}

// ---------------- host ----------------
static void* symaddr(const void* sym) {
    void* p = nullptr;
    cudaGetSymbolAddress(&p, sym);
    return p;
}

extern "C" void kernel_launch(void* const* d_in, const int* in_sizes, int n_in,
                              void* d_out, int out_size) {
    const float* x1 = (const float*)d_in[0];
    const float* x2 = (const float*)d_in[1];
    const float* w  = (const float*)d_in[2];

    __half* an   = (__half*)symaddr(d_anh);
    __half* bn   = (__half*)symaddr(d_bnh);
    __half* Gxy  = (__half*)symaddr(d_Gxy);
    __half* Gyx  = (__half*)symaddr(d_Gyx);
    __half* Gxx  = (__half*)symaddr(d_Gxx);
    __half* Gyy  = (__half*)symaddr(d_Gyy);
    uint8_t* Gxy8 = (uint8_t*)symaddr(d_Gxy8);
    uint8_t* Gyx8 = (uint8_t*)symaddr(d_Gyx8);
    uint8_t* Gxx8 = (uint8_t*)symaddr(d_Gxx8);
    uint8_t* Gyy8 = (uint8_t*)symaddr(d_Gyy8);
    float* fb  = (float*)symaddr(d_f);
    float* gb  = (float*)symaddr(d_g);
    float* xb  = (float*)symaddr(d_fxx);
    float* yb  = (float*)symaddr(d_gyy);
    float* ffin = (float*)symaddr(d_ffin);
    float* gfin = (float*)symaddr(d_gfin);
    float* xfin = (float*)symaddr(d_xfin);
    float* yfin = (float*)symaddr(d_yfin);

    cudaFuncSetAttribute(gemm_mma, cudaFuncAttributeMaxDynamicSharedMemorySize, GEMM_SMEM);
    cudaFuncSetAttribute(softmin4, cudaFuncAttributeMaxDynamicSharedMemorySize, SM_SOFTMIN);
    cudaFuncSetAttribute(softmin8, cudaFuncAttributeMaxDynamicSharedMemorySize, SM_SOFTMIN);

    wprep_kernel<<<1, DIM>>>(w);
    rownorm_kernel<<<2 * NPTS, DIM>>>(x1, x2);
    zero_kernel<<<NPTS / 256, 256>>>();

    {
        GArgs ga;
        ga.A[0] = an; ga.B[0] = bn; ga.C[0] = Gxy; ga.CT[0] = Gyx;
        ga.C8[0] = Gxy8; ga.CT8[0] = Gyx8; ga.sym[0] = 0;
        ga.A[1] = an; ga.B[1] = an; ga.C[1] = Gxx; ga.CT[1] = Gxx;
        ga.C8[1] = Gxx8; ga.CT8[1] = Gxx8; ga.sym[1] = 1;
        ga.A[2] = bn; ga.B[2] = bn; ga.C[2] = Gyy; ga.CT[2] = Gyy;
        ga.C8[2] = Gyy8; ga.CT8[2] = Gyy8; ga.sym[2] = 1;
        gemm_mma<<<dim3(NPTS / 128, NPTS / 128, 3), 256, GEMM_SMEM>>>(ga);
    }

    const float eps_list[10] = {4.0f, 1.0f, 0.25f, 0.0625f, 0.015625f,
                                0.00390625f, 0.0025f, 0.0025f, 0.0025f, 0.0025f};
    int cur = 0;

    // iterations 0..3 (eps >= sigma): fp8 softmin
    for (int i = 0; i < 4; ++i) {
        int nxt = 1 - cur;
        SM8Args a;
        a.G[0] = Gxx8; a.pot[0] = xb + cur * NPTS; a.oldpot[0] = xb + cur * NPTS; a.out[0] = xb + nxt * NPTS; a.avg[0] = 1;
        a.G[1] = Gyy8; a.pot[1] = yb + cur * NPTS; a.oldpot[1] = yb + cur * NPTS; a.out[1] = yb + nxt * NPTS; a.avg[1] = 1;
        a.G[2] = Gxy8; a.pot[2] = gb + cur * NPTS; a.oldpot[2] = nullptr;         a.out[2] = fb + nxt * NPTS; a.avg[2] = 0;
        a.G[3] = Gyx8; a.pot[3] = fb + cur * NPTS; a.oldpot[3] = nullptr;         a.out[3] = gb + nxt * NPTS; a.avg[3] = 0;
        softmin8<<<dim3(NPTS / RPB8, 4), 256, SM_SOFTMIN>>>(a, eps_list[i]);
        cur = nxt;
    }

    // iterations 4..9: fp16 softmin
    for (int i = 4; i < 10; ++i) {
        int nxt = 1 - cur;
        SMArgs a;
        a.G[0] = Gxx;  a.pot[0] = xb + cur * NPTS; a.oldpot[0] = xb + cur * NPTS; a.out[0] = xb + nxt * NPTS; a.avg[0] = 1;
        a.G[1] = Gyy;  a.pot[1] = yb + cur * NPTS; a.oldpot[1] = yb + cur * NPTS; a.out[1] = yb + nxt * NPTS; a.avg[1] = 1;
        a.G[2] = Gxy;  a.pot[2] = gb + cur * NPTS; a.oldpot[2] = nullptr;         a.out[2] = fb + nxt * NPTS; a.avg[2] = 0;
        a.G[3] = Gyx;  a.pot[3] = fb + cur * NPTS; a.oldpot[3] = nullptr;         a.out[3] = gb + nxt * NPTS; a.avg[3] = 0;
        softmin4<<<dim3(NPTS / RPB, 4), 256, SM_SOFTMIN>>>(a, eps_list[i]);
        cur = nxt;
    }

    const float epsF = 0.0025f;
    {
        SMArgs a;
        a.G[0] = Gxy; a.pot[0] = gb + cur * NPTS; a.oldpot[0] = nullptr; a.out[0] = ffin; a.avg[0] = 0;
        a.G[1] = Gyx; a.pot[1] = fb + cur * NPTS; a.oldpot[1] = nullptr; a.out[1] = gfin; a.avg[1] = 0;
        a.G[2] = Gxx; a.pot[2] = xb + cur * NPTS; a.oldpot[2] = nullptr; a.out[2] = xfin; a.avg[2] = 0;
        a.G[3] = Gyy; a.pot[3] = yb + cur * NPTS; a.oldpot[3] = nullptr; a.out[3] = yfin; a.avg[3] = 0;
        softmin4<<<dim3(NPTS / RPB, 4), 256, SM_SOFTMIN>>>(a, epsF);
    }

    final_reduce<<<1, 1024>>>((float*)d_out);
}

// round 16
// speedup vs baseline: 1.4725x; 1.0012x over previous
#include <cuda_runtime.h>
#include <cuda_fp16.h>
#include <math.h>
#include <stdint.h>

#define NPTS 8192
#define DIM 256
#define KC 64
#define NCHUNK (DIM / KC)
#define RPB 4
#define RPB8 8
#define SM_SOFTMIN 65536
#define GEMM_SMEM 65536
#define FP8_SCALE 16.0f

// ---------------- static device scratch (no allocation allowed) ----------------
__device__ float   d_wc[DIM];
__device__ __half  d_anh[(size_t)NPTS * DIM];
__device__ __half  d_bnh[(size_t)NPTS * DIM];
__device__ __half  d_Gxy[(size_t)NPTS * NPTS];
__device__ __half  d_Gyx[(size_t)NPTS * NPTS];
__device__ __half  d_Gxx[(size_t)NPTS * NPTS];
__device__ __half  d_Gyy[(size_t)NPTS * NPTS];
__device__ uint8_t d_Gxy8[(size_t)NPTS * NPTS];   // e4m3, scaled x16
__device__ uint8_t d_Gyx8[(size_t)NPTS * NPTS];
__device__ uint8_t d_Gxx8[(size_t)NPTS * NPTS];
__device__ uint8_t d_Gyy8[(size_t)NPTS * NPTS];
__device__ float   d_f[2][NPTS];
__device__ float   d_g[2][NPTS];
__device__ float   d_fxx[2][NPTS];
__device__ float   d_gyy[2][NPTS];
__device__ float   d_ffin[NPTS], d_gfin[NPTS], d_xfin[NPTS], d_yfin[NPTS];

__device__ __forceinline__ float ex2f_fast(float x) {
    float y; asm("ex2.approx.ftz.f32 %0, %1;" : "=f"(y) : "f"(x)); return y;
}
__device__ __forceinline__ __half2 ex2_h2(__half2 x) {
    uint32_t r, xi = *(uint32_t*)&x;
    asm("ex2.approx.f16x2 %0, %1;" : "=r"(r) : "r"(xi));
    return *(__half2*)&r;
}
__device__ __forceinline__ uint32_t smem_u32(const void* p) {
    uint32_t a;
    asm("{ .reg .u64 t; cvta.to.shared.u64 t, %1; cvt.u32.u64 %0, t; }" : "=r"(a) : "l"(p));
    return a;
}
__device__ __forceinline__ void cp_async16(uint32_t dst, const void* src) {
    asm volatile("cp.async.cg.shared.global [%0], [%1], 16;" :: "r"(dst), "l"(src) : "memory");
}
__device__ __forceinline__ __half2 e4m3x2_to_h2(uint16_t v) {
    uint32_t r;
    asm("cvt.rn.f16x2.e4m3x2 %0, %1;" : "=r"(r) : "h"(v));
    return *(__half2*)&r;
}
__device__ __forceinline__ uint16_t h2_to_e4m3x2(uint32_t h2bits) {
    __half2 h = *(__half2*)&h2bits;
    h = __hmul2(h, __floats2half2_rn(FP8_SCALE, FP8_SCALE));
    uint16_t r;
    asm("cvt.rn.satfinite.e4m3x2.f16x2 %0, %1;" : "=h"(r) : "r"(*(uint32_t*)&h));
    return r;
}
#define LDMX4(r, addr)                                                          \
    asm volatile("ldmatrix.sync.aligned.m8n8.x4.shared.b16 {%0,%1,%2,%3}, [%4];" \
                 : "=r"((r)[0]), "=r"((r)[1]), "=r"((r)[2]), "=r"((r)[3])        \
                 : "r"(addr))

// ---------------- prep ----------------
__global__ void wprep_kernel(const float* __restrict__ w) {
    __shared__ float sh[DIM];
    int t = threadIdx.x;
    float c = fminf(fmaxf(w[t], 0.0f), 2.0f);
    sh[t] = c;
    __syncthreads();
    for (int off = DIM / 2; off > 0; off >>= 1) {
        if (t < off) sh[t] += sh[t + off];
        __syncthreads();
    }
    d_wc[t] = c * ((float)DIM / sh[0]);
}

__global__ void rownorm_kernel(const float* __restrict__ x1, const float* __restrict__ x2) {
    __shared__ float sh[DIM];
    int b = blockIdx.x, t = threadIdx.x;
    float v;
    if (b < NPTS) v = d_wc[t] * x1[(size_t)b * DIM + t];
    else          v = x2[(size_t)(b - NPTS) * DIM + t];
    sh[t] = v * v;
    __syncthreads();
    for (int off = DIM / 2; off > 0; off >>= 1) {
        if (t < off) sh[t] += sh[t + off];
        __syncthreads();
    }
    float inv = 1.0f / (sqrtf(sh[0]) + 1e-12f);
    __half h = __float2half_rn(v * inv);
    if (b < NPTS) d_anh[(size_t)b * DIM + t] = h;
    else          d_bnh[(size_t)(b - NPTS) * DIM + t] = h;
}

__global__ void zero_kernel() {
    int i = blockIdx.x * blockDim.x + threadIdx.x;
    if (i < NPTS) {
        d_f[0][i] = 0.0f; d_g[0][i] = 0.0f;
        d_fxx[0][i] = 0.0f; d_gyy[0][i] = 0.0f;
    }
}

// ---------------- HMMA GEMM: 3 problems, fp16 + fp8 outputs ----------------
struct GArgs {
    const __half* A[3];
    const __half* B[3];
    __half*       C[3];
    __half*       CT[3];
    uint8_t*      C8[3];
    uint8_t*      CT8[3];
    int           sym[3];
};

__global__ void __launch_bounds__(256, 2) gemm_mma(GArgs ga) {
    extern __shared__ char smem[];
    const int prob = blockIdx.z;
    const int btx = blockIdx.x, bty = blockIdx.y;
    const int sym = ga.sym[prob];
    if (sym && btx > bty) return;
    const __half* A   = ga.A[prob];
    const __half* B   = ga.B[prob];
    __half*       C   = ga.C[prob];
    __half*       CT  = ga.CT[prob];
    uint8_t*      C8  = ga.C8[prob];
    uint8_t*      CT8 = ga.CT8[prob];

    const uint32_t smem_base = smem_u32(smem);
    const int tid = threadIdx.x;
    const int wid = tid >> 5, lane = tid & 31;
    const int warp_m = wid >> 2, warp_n = wid & 3;
    const int rowBase = bty * 128;
    const int colBase = btx * 128;

    const int mat = lane >> 3, rin = lane & 7;
    const int a_row_in = (mat & 1) * 8 + rin;
    const int a_kh     = (mat >> 1) * 8;
    const int b_row_in = (mat >> 1) * 8 + rin;
    const int b_kh     = (mat & 1) * 8;

    float acc[4][4][4];
#pragma unroll
    for (int mi = 0; mi < 4; ++mi)
#pragma unroll
        for (int ni = 0; ni < 4; ++ni)
#pragma unroll
            for (int q = 0; q < 4; ++q) acc[mi][ni][q] = 0.0f;

#define ISSUE_CHUNK(c, b) do {                                                  \
        const __half* Asrc_ = A + (size_t)rowBase * DIM + (c) * KC;             \
        const __half* Bsrc_ = B + (size_t)colBase * DIM + (c) * KC;             \
        uint32_t Ab_ = smem_base + (b) * 32768;                                 \
        uint32_t Bb_ = Ab_ + 16384;                                             \
        _Pragma("unroll")                                                       \
        for (int q_ = 0; q_ < 4; ++q_) {                                        \
            int i_ = q_ * 256 + tid;                                            \
            int r_ = i_ >> 3, cw_ = i_ & 7;                                     \
            uint32_t off_ = r_ * 128 + (((uint32_t)(cw_ ^ (r_ & 7))) << 4);     \
            cp_async16(Ab_ + off_, Asrc_ + (size_t)r_ * DIM + cw_ * 8);         \
            cp_async16(Bb_ + off_, Bsrc_ + (size_t)r_ * DIM + cw_ * 8);         \
        }                                                                       \
        asm volatile("cp.async.commit_group;" ::: "memory");                    \
    } while (0)

    ISSUE_CHUNK(0, 0);
#pragma unroll
    for (int c = 0; c < NCHUNK; ++c) {
        if (c + 1 < NCHUNK) {
            ISSUE_CHUNK(c + 1, (c + 1) & 1);
            asm volatile("cp.async.wait_group 1;" ::: "memory");
        } else {
            asm volatile("cp.async.wait_group 0;" ::: "memory");
        }
        __syncthreads();
        uint32_t Ab = smem_base + (c & 1) * 32768;
        uint32_t Bb = Ab + 16384;
#pragma unroll
        for (int ks = 0; ks < 4; ++ks) {
            uint32_t bf[2][4];
#pragma unroll
            for (int p = 0; p < 2; ++p) {
                int nrow = warp_n * 32 + p * 16 + b_row_in;
                int kcol = ks * 16 + b_kh;
                uint32_t addr = Bb + nrow * 128 + ((uint32_t)((kcol >> 3) ^ (nrow & 7)) << 4);
                LDMX4(bf[p], addr);
            }
#pragma unroll
            for (int mi = 0; mi < 4; ++mi) {
                uint32_t af[4];
                int arow = warp_m * 64 + mi * 16 + a_row_in;
                int kcol = ks * 16 + a_kh;
                uint32_t addr = Ab + arow * 128 + ((uint32_t)((kcol >> 3) ^ (arow & 7)) << 4);
                LDMX4(af, addr);
#pragma unroll
                for (int ni = 0; ni < 4; ++ni) {
                    asm volatile(
                        "mma.sync.aligned.m16n8k16.row.col.f32.f16.f16.f32 "
                        "{%0,%1,%2,%3}, {%4,%5,%6,%7}, {%8,%9}, {%0,%1,%2,%3};"
                        : "+f"(acc[mi][ni][0]), "+f"(acc[mi][ni][1]),
                          "+f"(acc[mi][ni][2]), "+f"(acc[mi][ni][3])
                        : "r"(af[0]), "r"(af[1]), "r"(af[2]), "r"(af[3]),
                          "r"(bf[ni >> 1][(ni & 1) * 2]), "r"(bf[ni >> 1][(ni & 1) * 2 + 1]));
                }
            }
        }
        __syncthreads();
    }
#undef ISSUE_CHUNK

    __half* stage = (__half*)smem;
#pragma unroll
    for (int mi = 0; mi < 4; ++mi)
#pragma unroll
        for (int ni = 0; ni < 4; ++ni) {
            int row = warp_m * 64 + mi * 16 + (lane >> 2);
            int col = warp_n * 32 + ni * 8 + 2 * (lane & 3);
            __half2 lo = __floats2half2_rn(acc[mi][ni][0], acc[mi][ni][1]);
            __half2 hi = __floats2half2_rn(acc[mi][ni][2], acc[mi][ni][3]);
            *(__half2*)(stage + row * 136 + col)       = lo;
            *(__half2*)(stage + (row + 8) * 136 + col) = hi;
        }
    __syncthreads();
#pragma unroll
    for (int i = tid; i < 2048; i += 256) {
        int r = i >> 4, ch = i & 15;
        uint4 v = *(uint4*)(stage + r * 136 + ch * 8);
        *(uint4*)(C + (size_t)(rowBase + r) * NPTS + colBase + ch * 8) = v;
        uint16_t b0 = h2_to_e4m3x2(v.x);
        uint16_t b1 = h2_to_e4m3x2(v.y);
        uint16_t b2 = h2_to_e4m3x2(v.z);
        uint16_t b3 = h2_to_e4m3x2(v.w);
        uint2 pk;
        pk.x = (uint32_t)b0 | ((uint32_t)b1 << 16);
        pk.y = (uint32_t)b2 | ((uint32_t)b3 << 16);
        *(uint2*)(C8 + (size_t)(rowBase + r) * NPTS + colBase + ch * 8) = pk;
    }

    if (!(sym && btx == bty)) {
        __syncthreads();
#pragma unroll
        for (int mi = 0; mi < 4; ++mi)
#pragma unroll
            for (int ni = 0; ni < 4; ++ni) {
                int row = warp_m * 64 + mi * 16 + (lane >> 2);
                int col = warp_n * 32 + ni * 8 + 2 * (lane & 3);
                stage[col * 136 + row]           = __float2half_rn(acc[mi][ni][0]);
                stage[(col + 1) * 136 + row]     = __float2half_rn(acc[mi][ni][1]);
                stage[col * 136 + row + 8]       = __float2half_rn(acc[mi][ni][2]);
                stage[(col + 1) * 136 + row + 8] = __float2half_rn(acc[mi][ni][3]);
            }
        __syncthreads();
#pragma unroll
        for (int i = tid; i < 2048; i += 256) {
            int r = i >> 4, ch = i & 15;
            uint4 v = *(uint4*)(stage + r * 136 + ch * 8);
            *(uint4*)(CT + (size_t)(colBase + r) * NPTS + rowBase + ch * 8) = v;
            uint16_t b0 = h2_to_e4m3x2(v.x);
            uint16_t b1 = h2_to_e4m3x2(v.y);
            uint16_t b2 = h2_to_e4m3x2(v.z);
            uint16_t b3 = h2_to_e4m3x2(v.w);
            uint2 pk;
            pk.x = (uint32_t)b0 | ((uint32_t)b1 << 16);
            pk.y = (uint32_t)b2 | ((uint32_t)b3 << 16);
            *(uint2*)(CT8 + (size_t)(colBase + r) * NPTS + rowBase + ch * 8) = pk;
        }
    }
}

// ---------------- dense softmin fp16 (small eps; R12 proven) ----------------
struct SMArgs {
    const __half* G[4];
    const float*  pot[4];
    const float*  oldpot[4];
    float*        out[4];
    int           avg[4];
};

__global__ void __launch_bounds__(256, 3) softmin4(SMArgs args, float eps) {
    extern __shared__ char smg[];
    const uint32_t smg_u = smem_u32(smg);
    const int var  = blockIdx.y;
    const int row0 = blockIdx.x * RPB;
    const int tid  = threadIdx.x;
    const int lane = tid & 31, wid = tid >> 5;

    const float L2E = 1.4426950408889634f;
    const float c1 = L2E / eps;
    const float c0 = -c1;

    const __half* Gbase = args.G[var];
#pragma unroll
    for (int r = 0; r < RPB; ++r) {
        const __half* Gr = Gbase + (size_t)(row0 + r) * NPTS;
#pragma unroll
        for (int q = 0; q < 4; ++q) {
            int idx = q * 256 + tid;
            cp_async16(smg_u + r * 16384 + idx * 16, Gr + idx * 8);
        }
    }
    asm volatile("cp.async.commit_group;" ::: "memory");

    const float* pot = args.pot[var];
    float pp[32];
#pragma unroll
    for (int it = 0; it < 4; ++it) {
        int idx = it * 256 + tid;
        float4 a = ((const float4*)pot)[2 * idx];
        float4 b = ((const float4*)pot)[2 * idx + 1];
        pp[8 * it + 0] = fmaf(a.x, c1, c0); pp[8 * it + 1] = fmaf(a.y, c1, c0);
        pp[8 * it + 2] = fmaf(a.z, c1, c0); pp[8 * it + 3] = fmaf(a.w, c1, c0);
        pp[8 * it + 4] = fmaf(b.x, c1, c0); pp[8 * it + 5] = fmaf(b.y, c1, c0);
        pp[8 * it + 6] = fmaf(b.z, c1, c0); pp[8 * it + 7] = fmaf(b.w, c1, c0);
    }
    __half2 pph2[16];
#pragma unroll
    for (int j = 0; j < 16; ++j)
        pph2[j] = __floats2half2_rn(pp[2 * j], pp[2 * j + 1]);
    const __half2 c1h2 = __floats2half2_rn(c1, c1);

    asm volatile("cp.async.wait_group 0;" ::: "memory");

    __shared__ float sA[RPB][8];
    __shared__ float sS[RPB][8];

    float wtm[RPB];
#pragma unroll
    for (int r = 0; r < RPB; ++r) {
        __half2 mh = __floats2half2_rn(-60000.0f, -60000.0f);
#pragma unroll
        for (int it = 0; it < 4; ++it) {
            uint4 q = *(const uint4*)(smg + r * 16384 + (it * 256 + tid) * 16);
            const __half2* g2 = (const __half2*)&q;
#pragma unroll
            for (int k = 0; k < 4; ++k)
                mh = __hmax2(mh, __hfma2(g2[k], c1h2, pph2[it * 4 + k]));
        }
        float2 mf = __half22float2(mh);
        float tm = fmaxf(mf.x, mf.y);
#pragma unroll
        for (int off = 16; off > 0; off >>= 1)
            tm = fmaxf(tm, __shfl_xor_sync(0xffffffffu, tm, off));
        wtm[r] = tm;
        if (lane == 0) sA[r][wid] = tm;
    }
    __syncthreads();
    float M[RPB];
#pragma unroll
    for (int r = 0; r < RPB; ++r) {
        float m = sA[r][0];
#pragma unroll
        for (int i = 1; i < 8; ++i) m = fmaxf(m, sA[r][i]);
        M[r] = m;
    }

#pragma unroll
    for (int r = 0; r < RPB; ++r) {
        float s = 0.0f;
        if (wtm[r] >= M[r] - 36.0f) {
            float Mr = M[r];
            float s0 = 0.f, s1 = 0.f, s2 = 0.f, s3 = 0.f;
#pragma unroll
            for (int it = 0; it < 4; ++it) {
                uint4 q = *(const uint4*)(smg + r * 16384 + (it * 256 + tid) * 16);
                float2 g0 = __half22float2(*(const __half2*)&q.x);
                float2 g1 = __half22float2(*(const __half2*)&q.y);
                float2 g2 = __half22float2(*(const __half2*)&q.z);
                float2 g3 = __half22float2(*(const __half2*)&q.w);
                s0 += ex2f_fast(fmaf(g0.x, c1, pp[8 * it + 0]) - Mr);
                s1 += ex2f_fast(fmaf(g0.y, c1, pp[8 * it + 1]) - Mr);
                s2 += ex2f_fast(fmaf(g1.x, c1, pp[8 * it + 2]) - Mr);
                s3 += ex2f_fast(fmaf(g1.y, c1, pp[8 * it + 3]) - Mr);
                s0 += ex2f_fast(fmaf(g2.x, c1, pp[8 * it + 4]) - Mr);
                s1 += ex2f_fast(fmaf(g2.y, c1, pp[8 * it + 5]) - Mr);
                s2 += ex2f_fast(fmaf(g3.x, c1, pp[8 * it + 6]) - Mr);
                s3 += ex2f_fast(fmaf(g3.y, c1, pp[8 * it + 7]) - Mr);
            }
            s = (s0 + s1) + (s2 + s3);
        }
#pragma unroll
        for (int off = 16; off > 0; off >>= 1)
            s += __shfl_xor_sync(0xffffffffu, s, off);
        if (lane == 0) sS[r][wid] = s;
    }
    __syncthreads();

    if (tid < RPB) {
        int r = tid;
        float S = ((sS[r][0] + sS[r][1]) + (sS[r][2] + sS[r][3]))
                + ((sS[r][4] + sS[r][5]) + (sS[r][6] + sS[r][7]));
        const float LOGW = -9.010913347279288f;
        const float LN2  = 0.6931471805599453f;
        float lse = (M[r] + log2f(S)) * LN2;
        float res = -eps * (LOGW + lse);
        if (args.avg[var]) res = 0.5f * (args.oldpot[var][row0 + r] + res);
        args.out[var][row0 + r] = res;
    }
}

// ---------------- dense softmin fp8 (eps >= sigma), half2 exp pass B ----------------
struct SM8Args {
    const uint8_t* G[4];
    const float*   pot[4];
    const float*   oldpot[4];
    float*         out[4];
    int            avg[4];
};

__global__ void __launch_bounds__(256, 3) softmin8(SM8Args args, float eps) {
    extern __shared__ char smg[];               // RPB8 * 8 KB = 64 KB
    const uint32_t smg_u = smem_u32(smg);
    const int var  = blockIdx.y;
    const int row0 = blockIdx.x * RPB8;
    const int tid  = threadIdx.x;
    const int lane = tid & 31, wid = tid >> 5;

    const float L2E = 1.4426950408889634f;
    const float c1  = L2E / eps;
    const float c0  = -c1;
    const float c1g = c1 / FP8_SCALE;

    const uint8_t* Gbase = args.G[var];
#pragma unroll
    for (int r = 0; r < RPB8; ++r) {
        const uint8_t* Gr = Gbase + (size_t)(row0 + r) * NPTS;
#pragma unroll
        for (int q = 0; q < 2; ++q) {
            int idx = q * 256 + tid;
            cp_async16(smg_u + r * 8192 + idx * 16, Gr + idx * 16);
        }
    }
    asm volatile("cp.async.commit_group;" ::: "memory");

    const float* pot = args.pot[var];
    float pp[32];
#pragma unroll
    for (int q = 0; q < 2; ++q) {
        int cbase = q * 4096 + tid * 16;
#pragma unroll
        for (int e4 = 0; e4 < 4; ++e4) {
            float4 a = *(const float4*)(pot + cbase + e4 * 4);
            pp[q * 16 + e4 * 4 + 0] = fmaf(a.x, c1, c0);
            pp[q * 16 + e4 * 4 + 1] = fmaf(a.y, c1, c0);
            pp[q * 16 + e4 * 4 + 2] = fmaf(a.z, c1, c0);
            pp[q * 16 + e4 * 4 + 3] = fmaf(a.w, c1, c0);
        }
    }
    __half2 pph2[16];
#pragma unroll
    for (int j = 0; j < 16; ++j)
        pph2[j] = __floats2half2_rn(pp[2 * j], pp[2 * j + 1]);
    const __half2 cgh2 = __floats2half2_rn(c1g, c1g);

    asm volatile("cp.async.wait_group 0;" ::: "memory");

    __shared__ float sA[RPB8][8];
    __shared__ float sS[RPB8][8];

    // pass A: half2 max
    float wtm[RPB8];
#pragma unroll
    for (int r = 0; r < RPB8; ++r) {
        __half2 mh = __floats2half2_rn(-60000.0f, -60000.0f);
#pragma unroll
        for (int q = 0; q < 2; ++q) {
            uint4 v = *(const uint4*)(smg + r * 8192 + (q * 256 + tid) * 16);
            const uint32_t w[4] = {v.x, v.y, v.z, v.w};
#pragma unroll
            for (int k = 0; k < 4; ++k) {
                __half2 ha = e4m3x2_to_h2((uint16_t)(w[k] & 0xFFFFu));
                __half2 hb = e4m3x2_to_h2((uint16_t)(w[k] >> 16));
                mh = __hmax2(mh, __hfma2(ha, cgh2, pph2[q * 8 + 2 * k]));
                mh = __hmax2(mh, __hfma2(hb, cgh2, pph2[q * 8 + 2 * k + 1]));
            }
        }
        float2 mf = __half22float2(mh);
        float tm = fmaxf(mf.x, mf.y);
#pragma unroll
        for (int off = 16; off > 0; off >>= 1)
            tm = fmaxf(tm, __shfl_xor_sync(0xffffffffu, tm, off));
        wtm[r] = tm;
        if (lane == 0) sA[r][wid] = tm;
    }
    __syncthreads();
    float M[RPB8];
#pragma unroll
    for (int r = 0; r < RPB8; ++r) {
        float m = sA[r][0];
#pragma unroll
        for (int i = 1; i < 8; ++i) m = fmaxf(m, sA[r][i]);
        M[r] = m;
    }

    // pass B: half2 u-M, f16x2 exp (half the MUFU ops), fp32 accumulation
#pragma unroll
    for (int r = 0; r < RPB8; ++r) {
        float s = 0.0f;
        if (wtm[r] >= M[r] - 36.0f) {
            const __half2 Mh = __floats2half2_rn(M[r], M[r]);
            __half2 ppm2[16];
#pragma unroll
            for (int j = 0; j < 16; ++j) ppm2[j] = __hsub2(pph2[j], Mh);
            float s0 = 0.f, s1 = 0.f;
#pragma unroll
            for (int q = 0; q < 2; ++q) {
                uint4 v = *(const uint4*)(smg + r * 8192 + (q * 256 + tid) * 16);
                const uint32_t w[4] = {v.x, v.y, v.z, v.w};
#pragma unroll
                for (int k = 0; k < 4; ++k) {
                    __half2 ha = e4m3x2_to_h2((uint16_t)(w[k] & 0xFFFFu));
                    __half2 hb = e4m3x2_to_h2((uint16_t)(w[k] >> 16));
                    __half2 e1 = ex2_h2(__hfma2(ha, cgh2, ppm2[q * 8 + 2 * k]));
                    __half2 e2 = ex2_h2(__hfma2(hb, cgh2, ppm2[q * 8 + 2 * k + 1]));
                    float2 f1 = __half22float2(e1);
                    float2 f2 = __half22float2(e2);
                    s0 += f1.x + f2.x;
                    s1 += f1.y + f2.y;
                }
            }
            s = s0 + s1;
        }
#pragma unroll
        for (int off = 16; off > 0; off >>= 1)
            s += __shfl_xor_sync(0xffffffffu, s, off);
        if (lane == 0) sS[r][wid] = s;
    }
    __syncthreads();

    if (tid < RPB8) {
        int r = tid;
        float S = ((sS[r][0] + sS[r][1]) + (sS[r][2] + sS[r][3]))
                + ((sS[r][4] + sS[r][5]) + (sS[r][6] + sS[r][7]));
        const float LOGW = -9.010913347279288f;
        const float LN2  = 0.6931471805599453f;
        float lse = (M[r] + log2f(S)) * LN2;
        float res = -eps * (LOGW + lse);
        if (args.avg[var]) res = 0.5f * (args.oldpot[var][row0 + r] + res);
        args.out[var][row0 + r] = res;
    }
}

// ---------------- final reduction ----------------
__global__ void final_reduce(float* __restrict__ out) {
    __shared__ float sh[1024];
    int t = threadIdx.x;
    float s = 0.0f;
    for (int i = t; i < NPTS; i += 1024)
        s += (d_ffin[i] - d_xfin[i]) + (d_gfin[i] - d_yfin[i]);
    sh[t] = s;
    __syncthreads();
    for (int off = 512; off > 0; off >>= 1) {
        if (t < off) sh[t] += sh[t + off];
        __syncthreads();
    }
    if (t == 0) out[0] = sh[0] / (float)NPTS;
}

// ---------------- host ----------------
static void* symaddr(const void* sym) {
    void* p = nullptr;
    cudaGetSymbolAddress(&p, sym);
    return p;
}

extern "C" void kernel_launch(void* const* d_in, const int* in_sizes, int n_in,
                              void* d_out, int out_size) {
    const float* x1 = (const float*)d_in[0];
    const float* x2 = (const float*)d_in[1];
    const float* w  = (const float*)d_in[2];

    __half* an   = (__half*)symaddr(d_anh);
    __half* bn   = (__half*)symaddr(d_bnh);
    __half* Gxy  = (__half*)symaddr(d_Gxy);
    __half* Gyx  = (__half*)symaddr(d_Gyx);
    __half* Gxx  = (__half*)symaddr(d_Gxx);
    __half* Gyy  = (__half*)symaddr(d_Gyy);
    uint8_t* Gxy8 = (uint8_t*)symaddr(d_Gxy8);
    uint8_t* Gyx8 = (uint8_t*)symaddr(d_Gyx8);
    uint8_t* Gxx8 = (uint8_t*)symaddr(d_Gxx8);
    uint8_t* Gyy8 = (uint8_t*)symaddr(d_Gyy8);
    float* fb  = (float*)symaddr(d_f);
    float* gb  = (float*)symaddr(d_g);
    float* xb  = (float*)symaddr(d_fxx);
    float* yb  = (float*)symaddr(d_gyy);
    float* ffin = (float*)symaddr(d_ffin);
    float* gfin = (float*)symaddr(d_gfin);
    float* xfin = (float*)symaddr(d_xfin);
    float* yfin = (float*)symaddr(d_yfin);

    cudaFuncSetAttribute(gemm_mma, cudaFuncAttributeMaxDynamicSharedMemorySize, GEMM_SMEM);
    cudaFuncSetAttribute(softmin4, cudaFuncAttributeMaxDynamicSharedMemorySize, SM_SOFTMIN);
    cudaFuncSetAttribute(softmin8, cudaFuncAttributeMaxDynamicSharedMemorySize, SM_SOFTMIN);

    wprep_kernel<<<1, DIM>>>(w);
    rownorm_kernel<<<2 * NPTS, DIM>>>(x1, x2);
    zero_kernel<<<NPTS / 256, 256>>>();

    {
        GArgs ga;
        ga.A[0] = an; ga.B[0] = bn; ga.C[0] = Gxy; ga.CT[0] = Gyx;
        ga.C8[0] = Gxy8; ga.CT8[0] = Gyx8; ga.sym[0] = 0;
        ga.A[1] = an; ga.B[1] = an; ga.C[1] = Gxx; ga.CT[1] = Gxx;
        ga.C8[1] = Gxx8; ga.CT8[1] = Gxx8; ga.sym[1] = 1;
        ga.A[2] = bn; ga.B[2] = bn; ga.C[2] = Gyy; ga.CT[2] = Gyy;
        ga.C8[2] = Gyy8; ga.CT8[2] = Gyy8; ga.sym[2] = 1;
        gemm_mma<<<dim3(NPTS / 128, NPTS / 128, 3), 256, GEMM_SMEM>>>(ga);
    }

    const float eps_list[10] = {4.0f, 1.0f, 0.25f, 0.0625f, 0.015625f,
                                0.00390625f, 0.0025f, 0.0025f, 0.0025f, 0.0025f};
    int cur = 0;

    // iterations 0..3 (eps >= sigma): fp8 softmin
    for (int i = 0; i < 4; ++i) {
        int nxt = 1 - cur;
        SM8Args a;
        a.G[0] = Gxx8; a.pot[0] = xb + cur * NPTS; a.oldpot[0] = xb + cur * NPTS; a.out[0] = xb + nxt * NPTS; a.avg[0] = 1;
        a.G[1] = Gyy8; a.pot[1] = yb + cur * NPTS; a.oldpot[1] = yb + cur * NPTS; a.out[1] = yb + nxt * NPTS; a.avg[1] = 1;
        a.G[2] = Gxy8; a.pot[2] = gb + cur * NPTS; a.oldpot[2] = nullptr;         a.out[2] = fb + nxt * NPTS; a.avg[2] = 0;
        a.G[3] = Gyx8; a.pot[3] = fb + cur * NPTS; a.oldpot[3] = nullptr;         a.out[3] = gb + nxt * NPTS; a.avg[3] = 0;
        softmin8<<<dim3(NPTS / RPB8, 4), 256, SM_SOFTMIN>>>(a, eps_list[i]);
        cur = nxt;
    }

    // iterations 4..9: fp16 softmin
    for (int i = 4; i < 10; ++i) {
        int nxt = 1 - cur;
        SMArgs a;
        a.G[0] = Gxx;  a.pot[0] = xb + cur * NPTS; a.oldpot[0] = xb + cur * NPTS; a.out[0] = xb + nxt * NPTS; a.avg[0] = 1;
        a.G[1] = Gyy;  a.pot[1] = yb + cur * NPTS; a.oldpot[1] = yb + cur * NPTS; a.out[1] = yb + nxt * NPTS; a.avg[1] = 1;
        a.G[2] = Gxy;  a.pot[2] = gb + cur * NPTS; a.oldpot[2] = nullptr;         a.out[2] = fb + nxt * NPTS; a.avg[2] = 0;
        a.G[3] = Gyx;  a.pot[3] = fb + cur * NPTS; a.oldpot[3] = nullptr;         a.out[3] = gb + nxt * NPTS; a.avg[3] = 0;
        softmin4<<<dim3(NPTS / RPB, 4), 256, SM_SOFTMIN>>>(a, eps_list[i]);
        cur = nxt;
    }

    const float epsF = 0.0025f;
    {
        SMArgs a;
        a.G[0] = Gxy; a.pot[0] = gb + cur * NPTS; a.oldpot[0] = nullptr; a.out[0] = ffin; a.avg[0] = 0;
        a.G[1] = Gyx; a.pot[1] = fb + cur * NPTS; a.oldpot[1] = nullptr; a.out[1] = gfin; a.avg[1] = 0;
        a.G[2] = Gxx; a.pot[2] = xb + cur * NPTS; a.oldpot[2] = nullptr; a.out[2] = xfin; a.avg[2] = 0;
        a.G[3] = Gyy; a.pot[3] = yb + cur * NPTS; a.oldpot[3] = nullptr; a.out[3] = yfin; a.avg[3] = 0;
        softmin4<<<dim3(NPTS / RPB, 4), 256, SM_SOFTMIN>>>(a, epsF);
    }

    final_reduce<<<1, 1024>>>((float*)d_out);
}

// round 17
// speedup vs baseline: 1.6394x; 1.1134x over previous
#include <cuda_runtime.h>
#include <cuda_fp16.h>
#include <math.h>
#include <stdint.h>

#define NPTS 8192
#define DIM 256
#define KC 64
#define NCHUNK (DIM / KC)
#define RPB 4
#define RPB8 8
#define SM_SOFTMIN 65536
#define GEMM_SMEM 65536
#define FP8_SCALE 16.0f

// ---------------- static device scratch (no allocation allowed) ----------------
__device__ float   d_wc[DIM];
__device__ __half  d_anh[(size_t)NPTS * DIM];
__device__ __half  d_bnh[(size_t)NPTS * DIM];
__device__ __half  d_Gxy[(size_t)NPTS * NPTS];
__device__ __half  d_Gyx[(size_t)NPTS * NPTS];
__device__ __half  d_Gxx[(size_t)NPTS * NPTS];
__device__ __half  d_Gyy[(size_t)NPTS * NPTS];
__device__ uint8_t d_Gxy8[(size_t)NPTS * NPTS];   // e4m3, scaled x16
__device__ uint8_t d_Gyx8[(size_t)NPTS * NPTS];
__device__ uint8_t d_Gxx8[(size_t)NPTS * NPTS];
__device__ uint8_t d_Gyy8[(size_t)NPTS * NPTS];
__device__ float   d_f[2][NPTS];
__device__ float   d_g[2][NPTS];
__device__ float   d_fxx[2][NPTS];
__device__ float   d_gyy[2][NPTS];
__device__ float   d_ffin[NPTS], d_gfin[NPTS], d_xfin[NPTS], d_yfin[NPTS];

__device__ __forceinline__ float ex2f_fast(float x) {
    float y; asm("ex2.approx.ftz.f32 %0, %1;" : "=f"(y) : "f"(x)); return y;
}
__device__ __forceinline__ uint32_t smem_u32(const void* p) {
    uint32_t a;
    asm("{ .reg .u64 t; cvta.to.shared.u64 t, %1; cvt.u32.u64 %0, t; }" : "=r"(a) : "l"(p));
    return a;
}
__device__ __forceinline__ void cp_async16(uint32_t dst, const void* src) {
    asm volatile("cp.async.cg.shared.global [%0], [%1], 16;" :: "r"(dst), "l"(src) : "memory");
}
__device__ __forceinline__ __half2 e4m3x2_to_h2(uint16_t v) {
    uint32_t r;
    asm("cvt.rn.f16x2.e4m3x2 %0, %1;" : "=r"(r) : "h"(v));
    return *(__half2*)&r;
}
__device__ __forceinline__ uint16_t h2_to_e4m3x2(uint32_t h2bits) {
    __half2 h = *(__half2*)&h2bits;
    h = __hmul2(h, __floats2half2_rn(FP8_SCALE, FP8_SCALE));
    uint16_t r;
    asm("cvt.rn.satfinite.e4m3x2.f16x2 %0, %1;" : "=h"(r) : "r"(*(uint32_t*)&h));
    return r;
}
#define LDMX4(r, addr)                                                          \
    asm volatile("ldmatrix.sync.aligned.m8n8.x4.shared.b16 {%0,%1,%2,%3}, [%4];" \
                 : "=r"((r)[0]), "=r"((r)[1]), "=r"((r)[2]), "=r"((r)[3])        \
                 : "r"(addr))

// ---------------- prep ----------------
__global__ void wprep_kernel(const float* __restrict__ w) {
    __shared__ float sh[DIM];
    int t = threadIdx.x;
    float c = fminf(fmaxf(w[t], 0.0f), 2.0f);
    sh[t] = c;
    __syncthreads();
    for (int off = DIM / 2; off > 0; off >>= 1) {
        if (t < off) sh[t] += sh[t + off];
        __syncthreads();
    }
    d_wc[t] = c * ((float)DIM / sh[0]);
}

__global__ void rownorm_kernel(const float* __restrict__ x1, const float* __restrict__ x2) {
    __shared__ float sh[DIM];
    int b = blockIdx.x, t = threadIdx.x;
    float v;
    if (b < NPTS) v = d_wc[t] * x1[(size_t)b * DIM + t];
    else          v = x2[(size_t)(b - NPTS) * DIM + t];
    sh[t] = v * v;
    __syncthreads();
    for (int off = DIM / 2; off > 0; off >>= 1) {
        if (t < off) sh[t] += sh[t + off];
        __syncthreads();
    }
    float inv = 1.0f / (sqrtf(sh[0]) + 1e-12f);
    __half h = __float2half_rn(v * inv);
    if (b < NPTS) d_anh[(size_t)b * DIM + t] = h;
    else          d_bnh[(size_t)(b - NPTS) * DIM + t] = h;
}

__global__ void zero_kernel() {
    int i = blockIdx.x * blockDim.x + threadIdx.x;
    if (i < NPTS) {
        d_f[0][i] = 0.0f; d_g[0][i] = 0.0f;
        d_fxx[0][i] = 0.0f; d_gyy[0][i] = 0.0f;
    }
}

// ---------------- HMMA GEMM: 3 problems, fp16 + fp8 outputs ----------------
struct GArgs {
    const __half* A[3];
    const __half* B[3];
    __half*       C[3];
    __half*       CT[3];
    uint8_t*      C8[3];
    uint8_t*      CT8[3];
    int           sym[3];
};

__global__ void __launch_bounds__(256, 2) gemm_mma(GArgs ga) {
    extern __shared__ char smem[];
    const int prob = blockIdx.z;
    const int btx = blockIdx.x, bty = blockIdx.y;
    const int sym = ga.sym[prob];
    if (sym && btx > bty) return;
    const __half* A   = ga.A[prob];
    const __half* B   = ga.B[prob];
    __half*       C   = ga.C[prob];
    __half*       CT  = ga.CT[prob];
    uint8_t*      C8  = ga.C8[prob];
    uint8_t*      CT8 = ga.CT8[prob];

    const uint32_t smem_base = smem_u32(smem);
    const int tid = threadIdx.x;
    const int wid = tid >> 5, lane = tid & 31;
    const int warp_m = wid >> 2, warp_n = wid & 3;
    const int rowBase = bty * 128;
    const int colBase = btx * 128;

    const int mat = lane >> 3, rin = lane & 7;
    const int a_row_in = (mat & 1) * 8 + rin;
    const int a_kh     = (mat >> 1) * 8;
    const int b_row_in = (mat >> 1) * 8 + rin;
    const int b_kh     = (mat & 1) * 8;

    float acc[4][4][4];
#pragma unroll
    for (int mi = 0; mi < 4; ++mi)
#pragma unroll
        for (int ni = 0; ni < 4; ++ni)
#pragma unroll
            for (int q = 0; q < 4; ++q) acc[mi][ni][q] = 0.0f;

#define ISSUE_CHUNK(c, b) do {                                                  \
        const __half* Asrc_ = A + (size_t)rowBase * DIM + (c) * KC;             \
        const __half* Bsrc_ = B + (size_t)colBase * DIM + (c) * KC;             \
        uint32_t Ab_ = smem_base + (b) * 32768;                                 \
        uint32_t Bb_ = Ab_ + 16384;                                             \
        _Pragma("unroll")                                                       \
        for (int q_ = 0; q_ < 4; ++q_) {                                        \
            int i_ = q_ * 256 + tid;                                            \
            int r_ = i_ >> 3, cw_ = i_ & 7;                                     \
            uint32_t off_ = r_ * 128 + (((uint32_t)(cw_ ^ (r_ & 7))) << 4);     \
            cp_async16(Ab_ + off_, Asrc_ + (size_t)r_ * DIM + cw_ * 8);         \
            cp_async16(Bb_ + off_, Bsrc_ + (size_t)r_ * DIM + cw_ * 8);         \
        }                                                                       \
        asm volatile("cp.async.commit_group;" ::: "memory");                    \
    } while (0)

    ISSUE_CHUNK(0, 0);
#pragma unroll
    for (int c = 0; c < NCHUNK; ++c) {
        if (c + 1 < NCHUNK) {
            ISSUE_CHUNK(c + 1, (c + 1) & 1);
            asm volatile("cp.async.wait_group 1;" ::: "memory");
        } else {
            asm volatile("cp.async.wait_group 0;" ::: "memory");
        }
        __syncthreads();
        uint32_t Ab = smem_base + (c & 1) * 32768;
        uint32_t Bb = Ab + 16384;
#pragma unroll
        for (int ks = 0; ks < 4; ++ks) {
            uint32_t bf[2][4];
#pragma unroll
            for (int p = 0; p < 2; ++p) {
                int nrow = warp_n * 32 + p * 16 + b_row_in;
                int kcol = ks * 16 + b_kh;
                uint32_t addr = Bb + nrow * 128 + ((uint32_t)((kcol >> 3) ^ (nrow & 7)) << 4);
                LDMX4(bf[p], addr);
            }
#pragma unroll
            for (int mi = 0; mi < 4; ++mi) {
                uint32_t af[4];
                int arow = warp_m * 64 + mi * 16 + a_row_in;
                int kcol = ks * 16 + a_kh;
                uint32_t addr = Ab + arow * 128 + ((uint32_t)((kcol >> 3) ^ (arow & 7)) << 4);
                LDMX4(af, addr);
#pragma unroll
                for (int ni = 0; ni < 4; ++ni) {
                    asm volatile(
                        "mma.sync.aligned.m16n8k16.row.col.f32.f16.f16.f32 "
                        "{%0,%1,%2,%3}, {%4,%5,%6,%7}, {%8,%9}, {%0,%1,%2,%3};"
                        : "+f"(acc[mi][ni][0]), "+f"(acc[mi][ni][1]),
                          "+f"(acc[mi][ni][2]), "+f"(acc[mi][ni][3])
                        : "r"(af[0]), "r"(af[1]), "r"(af[2]), "r"(af[3]),
                          "r"(bf[ni >> 1][(ni & 1) * 2]), "r"(bf[ni >> 1][(ni & 1) * 2 + 1]));
                }
            }
        }
        __syncthreads();
    }
#undef ISSUE_CHUNK

    __half* stage = (__half*)smem;
#pragma unroll
    for (int mi = 0; mi < 4; ++mi)
#pragma unroll
        for (int ni = 0; ni < 4; ++ni) {
            int row = warp_m * 64 + mi * 16 + (lane >> 2);
            int col = warp_n * 32 + ni * 8 + 2 * (lane & 3);
            __half2 lo = __floats2half2_rn(acc[mi][ni][0], acc[mi][ni][1]);
            __half2 hi = __floats2half2_rn(acc[mi][ni][2], acc[mi][ni][3]);
            *(__half2*)(stage + row * 136 + col)       = lo;
            *(__half2*)(stage + (row + 8) * 136 + col) = hi;
        }
    __syncthreads();
#pragma unroll
    for (int i = tid; i < 2048; i += 256) {
        int r = i >> 4, ch = i & 15;
        uint4 v = *(uint4*)(stage + r * 136 + ch * 8);
        *(uint4*)(C + (size_t)(rowBase + r) * NPTS + colBase + ch * 8) = v;
        uint16_t b0 = h2_to_e4m3x2(v.x);
        uint16_t b1 = h2_to_e4m3x2(v.y);
        uint16_t b2 = h2_to_e4m3x2(v.z);
        uint16_t b3 = h2_to_e4m3x2(v.w);
        uint2 pk;
        pk.x = (uint32_t)b0 | ((uint32_t)b1 << 16);
        pk.y = (uint32_t)b2 | ((uint32_t)b3 << 16);
        *(uint2*)(C8 + (size_t)(rowBase + r) * NPTS + colBase + ch * 8) = pk;
    }

    if (!(sym && btx == bty)) {
        __syncthreads();
#pragma unroll
        for (int mi = 0; mi < 4; ++mi)
#pragma unroll
            for (int ni = 0; ni < 4; ++ni) {
                int row = warp_m * 64 + mi * 16 + (lane >> 2);
                int col = warp_n * 32 + ni * 8 + 2 * (lane & 3);
                stage[col * 136 + row]           = __float2half_rn(acc[mi][ni][0]);
                stage[(col + 1) * 136 + row]     = __float2half_rn(acc[mi][ni][1]);
                stage[col * 136 + row + 8]       = __float2half_rn(acc[mi][ni][2]);
                stage[(col + 1) * 136 + row + 8] = __float2half_rn(acc[mi][ni][3]);
            }
        __syncthreads();
#pragma unroll
        for (int i = tid; i < 2048; i += 256) {
            int r = i >> 4, ch = i & 15;
            uint4 v = *(uint4*)(stage + r * 136 + ch * 8);
            *(uint4*)(CT + (size_t)(colBase + r) * NPTS + rowBase + ch * 8) = v;
            uint16_t b0 = h2_to_e4m3x2(v.x);
            uint16_t b1 = h2_to_e4m3x2(v.y);
            uint16_t b2 = h2_to_e4m3x2(v.z);
            uint16_t b3 = h2_to_e4m3x2(v.w);
            uint2 pk;
            pk.x = (uint32_t)b0 | ((uint32_t)b1 << 16);
            pk.y = (uint32_t)b2 | ((uint32_t)b3 << 16);
            *(uint2*)(CT8 + (size_t)(colBase + r) * NPTS + rowBase + ch * 8) = pk;
        }
    }
}

// ---------------- dense softmin fp16 (small eps; R12 proven) ----------------
struct SMArgs {
    const __half* G[4];
    const float*  pot[4];
    const float*  oldpot[4];
    float*        out[4];
    int           avg[4];
};

__global__ void __launch_bounds__(256, 3) softmin4(SMArgs args, float eps) {
    extern __shared__ char smg[];
    const uint32_t smg_u = smem_u32(smg);
    const int var  = blockIdx.y;
    const int row0 = blockIdx.x * RPB;
    const int tid  = threadIdx.x;
    const int lane = tid & 31, wid = tid >> 5;

    const float L2E = 1.4426950408889634f;
    const float c1 = L2E / eps;
    const float c0 = -c1;

    const __half* Gbase = args.G[var];
#pragma unroll
    for (int r = 0; r < RPB; ++r) {
        const __half* Gr = Gbase + (size_t)(row0 + r) * NPTS;
#pragma unroll
        for (int q = 0; q < 4; ++q) {
            int idx = q * 256 + tid;
            cp_async16(smg_u + r * 16384 + idx * 16, Gr + idx * 8);
        }
    }
    asm volatile("cp.async.commit_group;" ::: "memory");

    const float* pot = args.pot[var];
    float pp[32];
#pragma unroll
    for (int it = 0; it < 4; ++it) {
        int idx = it * 256 + tid;
        float4 a = ((const float4*)pot)[2 * idx];
        float4 b = ((const float4*)pot)[2 * idx + 1];
        pp[8 * it + 0] = fmaf(a.x, c1, c0); pp[8 * it + 1] = fmaf(a.y, c1, c0);
        pp[8 * it + 2] = fmaf(a.z, c1, c0); pp[8 * it + 3] = fmaf(a.w, c1, c0);
        pp[8 * it + 4] = fmaf(b.x, c1, c0); pp[8 * it + 5] = fmaf(b.y, c1, c0);
        pp[8 * it + 6] = fmaf(b.z, c1, c0); pp[8 * it + 7] = fmaf(b.w, c1, c0);
    }
    __half2 pph2[16];
#pragma unroll
    for (int j = 0; j < 16; ++j)
        pph2[j] = __floats2half2_rn(pp[2 * j], pp[2 * j + 1]);
    const __half2 c1h2 = __floats2half2_rn(c1, c1);

    asm volatile("cp.async.wait_group 0;" ::: "memory");

    __shared__ float sA[RPB][8];
    __shared__ float sS[RPB][8];

    float wtm[RPB];
#pragma unroll
    for (int r = 0; r < RPB; ++r) {
        __half2 mh = __floats2half2_rn(-60000.0f, -60000.0f);
#pragma unroll
        for (int it = 0; it < 4; ++it) {
            uint4 q = *(const uint4*)(smg + r * 16384 + (it * 256 + tid) * 16);
            const __half2* g2 = (const __half2*)&q;
#pragma unroll
            for (int k = 0; k < 4; ++k)
                mh = __hmax2(mh, __hfma2(g2[k], c1h2, pph2[it * 4 + k]));
        }
        float2 mf = __half22float2(mh);
        float tm = fmaxf(mf.x, mf.y);
#pragma unroll
        for (int off = 16; off > 0; off >>= 1)
            tm = fmaxf(tm, __shfl_xor_sync(0xffffffffu, tm, off));
        wtm[r] = tm;
        if (lane == 0) sA[r][wid] = tm;
    }
    __syncthreads();
    float M[RPB];
#pragma unroll
    for (int r = 0; r < RPB; ++r) {
        float m = sA[r][0];
#pragma unroll
        for (int i = 1; i < 8; ++i) m = fmaxf(m, sA[r][i]);
        M[r] = m;
    }

#pragma unroll
    for (int r = 0; r < RPB; ++r) {
        float s = 0.0f;
        if (wtm[r] >= M[r] - 36.0f) {
            float Mr = M[r];
            float s0 = 0.f, s1 = 0.f, s2 = 0.f, s3 = 0.f;
#pragma unroll
            for (int it = 0; it < 4; ++it) {
                uint4 q = *(const uint4*)(smg + r * 16384 + (it * 256 + tid) * 16);
                float2 g0 = __half22float2(*(const __half2*)&q.x);
                float2 g1 = __half22float2(*(const __half2*)&q.y);
                float2 g2 = __half22float2(*(const __half2*)&q.z);
                float2 g3 = __half22float2(*(const __half2*)&q.w);
                s0 += ex2f_fast(fmaf(g0.x, c1, pp[8 * it + 0]) - Mr);
                s1 += ex2f_fast(fmaf(g0.y, c1, pp[8 * it + 1]) - Mr);
                s2 += ex2f_fast(fmaf(g1.x, c1, pp[8 * it + 2]) - Mr);
                s3 += ex2f_fast(fmaf(g1.y, c1, pp[8 * it + 3]) - Mr);
                s0 += ex2f_fast(fmaf(g2.x, c1, pp[8 * it + 4]) - Mr);
                s1 += ex2f_fast(fmaf(g2.y, c1, pp[8 * it + 5]) - Mr);
                s2 += ex2f_fast(fmaf(g3.x, c1, pp[8 * it + 6]) - Mr);
                s3 += ex2f_fast(fmaf(g3.y, c1, pp[8 * it + 7]) - Mr);
            }
            s = (s0 + s1) + (s2 + s3);
        }
#pragma unroll
        for (int off = 16; off > 0; off >>= 1)
            s += __shfl_xor_sync(0xffffffffu, s, off);
        if (lane == 0) sS[r][wid] = s;
    }
    __syncthreads();

    if (tid < RPB) {
        int r = tid;
        float S = ((sS[r][0] + sS[r][1]) + (sS[r][2] + sS[r][3]))
                + ((sS[r][4] + sS[r][5]) + (sS[r][6] + sS[r][7]));
        const float LOGW = -9.010913347279288f;
        const float LN2  = 0.6931471805599453f;
        float lse = (M[r] + log2f(S)) * LN2;
        float res = -eps * (LOGW + lse);
        if (args.avg[var]) res = 0.5f * (args.oldpot[var][row0 + r] + res);
        args.out[var][row0 + r] = res;
    }
}

// ---------------- dense softmin fp8 (eps >= sigma): SINGLE PASS with static offset ----
// LSE shift K = max(pp) + 1.1*c1 >= max u (since G <= 1.0625 after fp8 round).
// Slack K - u_max <= 2.1*c1 <= 49 log2 at eps=0.0625 -> all terms exact in fp32.
struct SM8Args {
    const uint8_t* G[4];
    const float*   pot[4];
    const float*   oldpot[4];
    float*         out[4];
    int            avg[4];
};

__global__ void __launch_bounds__(256, 3) softmin8(SM8Args args, float eps) {
    extern __shared__ char smg[];               // RPB8 * 8 KB = 64 KB
    const uint32_t smg_u = smem_u32(smg);
    const int var  = blockIdx.y;
    const int row0 = blockIdx.x * RPB8;
    const int tid  = threadIdx.x;
    const int lane = tid & 31, wid = tid >> 5;

    const float L2E = 1.4426950408889634f;
    const float c1  = L2E / eps;
    const float c0  = -c1;
    const float c1g = c1 / FP8_SCALE;

    const uint8_t* Gbase = args.G[var];
#pragma unroll
    for (int r = 0; r < RPB8; ++r) {
        const uint8_t* Gr = Gbase + (size_t)(row0 + r) * NPTS;
#pragma unroll
        for (int q = 0; q < 2; ++q) {
            int idx = q * 256 + tid;
            cp_async16(smg_u + r * 8192 + idx * 16, Gr + idx * 16);
        }
    }
    asm volatile("cp.async.commit_group;" ::: "memory");

    // pot fold: this thread's 32 columns are q*4096 + tid*16 .. +15 for q=0,1
    const float* pot = args.pot[var];
    float pp[32];
#pragma unroll
    for (int q = 0; q < 2; ++q) {
        int cbase = q * 4096 + tid * 16;
#pragma unroll
        for (int e4 = 0; e4 < 4; ++e4) {
            float4 a = *(const float4*)(pot + cbase + e4 * 4);
            pp[q * 16 + e4 * 4 + 0] = fmaf(a.x, c1, c0);
            pp[q * 16 + e4 * 4 + 1] = fmaf(a.y, c1, c0);
            pp[q * 16 + e4 * 4 + 2] = fmaf(a.z, c1, c0);
            pp[q * 16 + e4 * 4 + 3] = fmaf(a.w, c1, c0);
        }
    }

    // block max of pp over ALL 8192 columns (each block covers every column once)
    __shared__ float sK[8];
    float mp = pp[0];
#pragma unroll
    for (int j = 1; j < 32; ++j) mp = fmaxf(mp, pp[j]);
#pragma unroll
    for (int off = 16; off > 0; off >>= 1)
        mp = fmaxf(mp, __shfl_xor_sync(0xffffffffu, mp, off));
    if (lane == 0) sK[wid] = mp;
    __syncthreads();
    float K = sK[0];
#pragma unroll
    for (int i = 1; i < 8; ++i) K = fmaxf(K, sK[i]);
    K += 1.1f * c1;     // covers G up to 1.1 (fp8 rounding of G<=1 gives <=1.0625)

    // fold K into pp
#pragma unroll
    for (int j = 0; j < 32; ++j) pp[j] -= K;

    asm volatile("cp.async.wait_group 0;" ::: "memory");

    __shared__ float sS[RPB8][8];

    // single pass: S = sum exp2(u - K), fp32 throughout
#pragma unroll
    for (int r = 0; r < RPB8; ++r) {
        float s0 = 0.f, s1 = 0.f, s2 = 0.f, s3 = 0.f;
#pragma unroll
        for (int q = 0; q < 2; ++q) {
            uint4 v = *(const uint4*)(smg + r * 8192 + (q * 256 + tid) * 16);
            const uint32_t w[4] = {v.x, v.y, v.z, v.w};
#pragma unroll
            for (int k = 0; k < 4; ++k) {
                float2 ga = __half22float2(e4m3x2_to_h2((uint16_t)(w[k] & 0xFFFFu)));
                float2 gb = __half22float2(e4m3x2_to_h2((uint16_t)(w[k] >> 16)));
                s0 += ex2f_fast(fmaf(ga.x, c1g, pp[q * 16 + 4 * k + 0]));
                s1 += ex2f_fast(fmaf(ga.y, c1g, pp[q * 16 + 4 * k + 1]));
                s2 += ex2f_fast(fmaf(gb.x, c1g, pp[q * 16 + 4 * k + 2]));
                s3 += ex2f_fast(fmaf(gb.y, c1g, pp[q * 16 + 4 * k + 3]));
            }
        }
        float s = (s0 + s1) + (s2 + s3);
#pragma unroll
        for (int off = 16; off > 0; off >>= 1)
            s += __shfl_xor_sync(0xffffffffu, s, off);
        if (lane == 0) sS[r][wid] = s;
    }
    __syncthreads();

    if (tid < RPB8) {
        int r = tid;
        float S = ((sS[r][0] + sS[r][1]) + (sS[r][2] + sS[r][3]))
                + ((sS[r][4] + sS[r][5]) + (sS[r][6] + sS[r][7]));
        const float LOGW = -9.010913347279288f;
        const float LN2  = 0.6931471805599453f;
        float lse = (K + log2f(S)) * LN2;
        float res = -eps * (LOGW + lse);
        if (args.avg[var]) res = 0.5f * (args.oldpot[var][row0 + r] + res);
        args.out[var][row0 + r] = res;
    }
}

// ---------------- final reduction ----------------
__global__ void final_reduce(float* __restrict__ out) {
    __shared__ float sh[1024];
    int t = threadIdx.x;
    float s = 0.0f;
    for (int i = t; i < NPTS; i += 1024)
        s += (d_ffin[i] - d_xfin[i]) + (d_gfin[i] - d_yfin[i]);
    sh[t] = s;
    __syncthreads();
    for (int off = 512; off > 0; off >>= 1) {
        if (t < off) sh[t] += sh[t + off];
        __syncthreads();
    }
    if (t == 0) out[0] = sh[0] / (float)NPTS;
}

// ---------------- host ----------------
static void* symaddr(const void* sym) {
    void* p = nullptr;
    cudaGetSymbolAddress(&p, sym);
    return p;
}

extern "C" void kernel_launch(void* const* d_in, const int* in_sizes, int n_in,
                              void* d_out, int out_size) {
    const float* x1 = (const float*)d_in[0];
    const float* x2 = (const float*)d_in[1];
    const float* w  = (const float*)d_in[2];

    __half* an   = (__half*)symaddr(d_anh);
    __half* bn   = (__half*)symaddr(d_bnh);
    __half* Gxy  = (__half*)symaddr(d_Gxy);
    __half* Gyx  = (__half*)symaddr(d_Gyx);
    __half* Gxx  = (__half*)symaddr(d_Gxx);
    __half* Gyy  = (__half*)symaddr(d_Gyy);
    uint8_t* Gxy8 = (uint8_t*)symaddr(d_Gxy8);
    uint8_t* Gyx8 = (uint8_t*)symaddr(d_Gyx8);
    uint8_t* Gxx8 = (uint8_t*)symaddr(d_Gxx8);
    uint8_t* Gyy8 = (uint8_t*)symaddr(d_Gyy8);
    float* fb  = (float*)symaddr(d_f);
    float* gb  = (float*)symaddr(d_g);
    float* xb  = (float*)symaddr(d_fxx);
    float* yb  = (float*)symaddr(d_gyy);
    float* ffin = (float*)symaddr(d_ffin);
    float* gfin = (float*)symaddr(d_gfin);
    float* xfin = (float*)symaddr(d_xfin);
    float* yfin = (float*)symaddr(d_yfin);

    cudaFuncSetAttribute(gemm_mma, cudaFuncAttributeMaxDynamicSharedMemorySize, GEMM_SMEM);
    cudaFuncSetAttribute(softmin4, cudaFuncAttributeMaxDynamicSharedMemorySize, SM_SOFTMIN);
    cudaFuncSetAttribute(softmin8, cudaFuncAttributeMaxDynamicSharedMemorySize, SM_SOFTMIN);

    wprep_kernel<<<1, DIM>>>(w);
    rownorm_kernel<<<2 * NPTS, DIM>>>(x1, x2);
    zero_kernel<<<NPTS / 256, 256>>>();

    {
        GArgs ga;
        ga.A[0] = an; ga.B[0] = bn; ga.C[0] = Gxy; ga.CT[0] = Gyx;
        ga.C8[0] = Gxy8; ga.CT8[0] = Gyx8; ga.sym[0] = 0;
        ga.A[1] = an; ga.B[1] = an; ga.C[1] = Gxx; ga.CT[1] = Gxx;
        ga.C8[1] = Gxx8; ga.CT8[1] = Gxx8; ga.sym[1] = 1;
        ga.A[2] = bn; ga.B[2] = bn; ga.C[2] = Gyy; ga.CT[2] = Gyy;
        ga.C8[2] = Gyy8; ga.CT8[2] = Gyy8; ga.sym[2] = 1;
        gemm_mma<<<dim3(NPTS / 128, NPTS / 128, 3), 256, GEMM_SMEM>>>(ga);
    }

    const float eps_list[10] = {4.0f, 1.0f, 0.25f, 0.0625f, 0.015625f,
                                0.00390625f, 0.0025f, 0.0025f, 0.0025f, 0.0025f};
    int cur = 0;

    // iterations 0..3 (eps >= sigma): fp8 single-pass softmin
    for (int i = 0; i < 4; ++i) {
        int nxt = 1 - cur;
        SM8Args a;
        a.G[0] = Gxx8; a.pot[0] = xb + cur * NPTS; a.oldpot[0] = xb + cur * NPTS; a.out[0] = xb + nxt * NPTS; a.avg[0] = 1;
        a.G[1] = Gyy8; a.pot[1] = yb + cur * NPTS; a.oldpot[1] = yb + cur * NPTS; a.out[1] = yb + nxt * NPTS; a.avg[1] = 1;
        a.G[2] = Gxy8; a.pot[2] = gb + cur * NPTS; a.oldpot[2] = nullptr;         a.out[2] = fb + nxt * NPTS; a.avg[2] = 0;
        a.G[3] = Gyx8; a.pot[3] = fb + cur * NPTS; a.oldpot[3] = nullptr;         a.out[3] = gb + nxt * NPTS; a.avg[3] = 0;
        softmin8<<<dim3(NPTS / RPB8, 4), 256, SM_SOFTMIN>>>(a, eps_list[i]);
        cur = nxt;
    }

    // iterations 4..9: fp16 softmin
    for (int i = 4; i < 10; ++i) {
        int nxt = 1 - cur;
        SMArgs a;
        a.G[0] = Gxx;  a.pot[0] = xb + cur * NPTS; a.oldpot[0] = xb + cur * NPTS; a.out[0] = xb + nxt * NPTS; a.avg[0] = 1;
        a.G[1] = Gyy;  a.pot[1] = yb + cur * NPTS; a.oldpot[1] = yb + cur * NPTS; a.out[1] = yb + nxt * NPTS; a.avg[1] = 1;
        a.G[2] = Gxy;  a.pot[2] = gb + cur * NPTS; a.oldpot[2] = nullptr;         a.out[2] = fb + nxt * NPTS; a.avg[2] = 0;
        a.G[3] = Gyx;  a.pot[3] = fb + cur * NPTS; a.oldpot[3] = nullptr;         a.out[3] = gb + nxt * NPTS; a.avg[3] = 0;
        softmin4<<<dim3(NPTS / RPB, 4), 256, SM_SOFTMIN>>>(a, eps_list[i]);
        cur = nxt;
    }

    const float epsF = 0.0025f;
    {
        SMArgs a;
        a.G[0] = Gxy; a.pot[0] = gb + cur * NPTS; a.oldpot[0] = nullptr; a.out[0] = ffin; a.avg[0] = 0;
        a.G[1] = Gyx; a.pot[1] = fb + cur * NPTS; a.oldpot[1] = nullptr; a.out[1] = gfin; a.avg[1] = 0;
        a.G[2] = Gxx; a.pot[2] = xb + cur * NPTS; a.oldpot[2] = nullptr; a.out[2] = xfin; a.avg[2] = 0;
        a.G[3] = Gyy; a.pot[3] = yb + cur * NPTS; a.oldpot[3] = nullptr; a.out[3] = yfin; a.avg[3] = 0;
        softmin4<<<dim3(NPTS / RPB, 4), 256, SM_SOFTMIN>>>(a, epsF);
    }

    final_reduce<<<1, 1024>>>((float*)d_out);
}